// round 4
// baseline (speedup 1.0000x reference)
#include <cuda_runtime.h>
#include <math.h>
#include <stdint.h>

// B=4, CIN=64, HID=64, H=W=64, K=3, N=9, D=256, INC=128, OUTC=256
// HP=WP=66, HW=4096, CN = INC*9 = 1152
#define HW4 4096
#define CN 1152

// ---------------- scratch ----------------
__device__ float  d_tmp1[4 * 128 * 256];               // [b][c][d]
__device__ float2 d_Ao2[4 * 256 * CN];                 // [b][o][k] {tf32 hi, tf32 lo}
__device__ float  d_bm[4 * 256];                       // [b][o]
__device__ int    d_idx[4 * 9 * HW4 * 4];              // [b][n][hw][4]
__device__ float  d_gw [4 * 9 * HW4 * 4];              // [b][n][hw][4]
__device__ float  d_xpad[4 * 128 * 66 * 66];           // [b][c][66][66]
__device__ float2 d_xoffT2[(size_t)4 * HW4 * CN];      // [b][hw][k] {hi, lo}  151MB
__device__ float  d_comb[4 * 256 * HW4];               // [b][o][hw]

// ---------------- helpers ----------------
__device__ __forceinline__ uint32_t smem_u32(const void* p) {
    uint32_t a;
    asm("{ .reg .u64 t; cvta.to.shared.u64 t, %1; cvt.u32.u64 %0, t; }" : "=r"(a) : "l"(p));
    return a;
}
__device__ __forceinline__ float to_tf32(float x) {
    uint32_t u;
    asm("cvt.rna.tf32.f32 %0, %1;" : "=r"(u) : "f"(x));
    return __uint_as_float(u);
}
__device__ __forceinline__ float2 split_tf32(float v) {
    float hi = to_tf32(v);
    float lo = to_tf32(v - hi);
    return make_float2(hi, lo);
}
#define CP_ASYNC16(dst, src) asm volatile("cp.async.cg.shared.global [%0], [%1], 16;" :: "r"(dst), "l"(src))
#define CP_COMMIT()          asm volatile("cp.async.commit_group;" ::: "memory")
#define CP_WAIT(n)           asm volatile("cp.async.wait_group %0;" :: "n"(n) : "memory")

__device__ __forceinline__ void mma_tf32(float* c, const uint32_t* a, const uint32_t* b) {
    asm volatile(
        "mma.sync.aligned.m16n8k8.row.col.f32.tf32.tf32.f32 "
        "{%0,%1,%2,%3}, {%4,%5,%6,%7}, {%8,%9}, {%0,%1,%2,%3};"
        : "+f"(c[0]), "+f"(c[1]), "+f"(c[2]), "+f"(c[3])
        : "r"(a[0]), "r"(a[1]), "r"(a[2]), "r"(a[3]), "r"(b[0]), "r"(b[1]));
}

// ---------------- 1. concat + ZeroPad2d(1) ----------------
__global__ void k_pad(const float* __restrict__ inp, const float* __restrict__ hcur) {
    int i = blockIdx.x * 256 + threadIdx.x;
    const int total = 4 * 128 * 66 * 66;
    if (i >= total) return;
    int wp = i % 66;
    int t = i / 66;
    int hp = t % 66; t /= 66;
    int c = t % 128; int b = t / 128;
    float v = 0.f;
    if (hp >= 1 && hp <= 64 && wp >= 1 && wp <= 64) {
        int sp = ((b * 64 + (c < 64 ? c : c - 64)) * 64 + (hp - 1)) * 64 + (wp - 1);
        v = (c < 64) ? inp[sp] : hcur[sp];
    }
    d_xpad[i] = v;
}

// ---------------- 2. hyper stage 1 ----------------
__global__ void k_w1(const float* __restrict__ meta, const float* __restrict__ w1w,
                     const float* __restrict__ w1b) {
    __shared__ float sm[1024];
    for (int i = threadIdx.x; i < 1024; i += 256) sm[i] = meta[i];
    __syncthreads();
    int gw = (blockIdx.x * 256 + threadIdx.x) >> 5;
    int lane = threadIdx.x & 31;
    const float* row = w1w + (size_t)gw * 256;
    float a0 = 0.f, a1 = 0.f, a2 = 0.f, a3 = 0.f;
    #pragma unroll
    for (int k = lane; k < 256; k += 32) {
        float wv = row[k];
        a0 += wv * sm[k];       a1 += wv * sm[256 + k];
        a2 += wv * sm[512 + k]; a3 += wv * sm[768 + k];
    }
    #pragma unroll
    for (int s = 16; s > 0; s >>= 1) {
        a0 += __shfl_xor_sync(~0u, a0, s); a1 += __shfl_xor_sync(~0u, a1, s);
        a2 += __shfl_xor_sync(~0u, a2, s); a3 += __shfl_xor_sync(~0u, a3, s);
    }
    if (lane == 0) {
        float bb = w1b[gw];
        d_tmp1[gw] = a0 + bb;          d_tmp1[32768 + gw] = a1 + bb;
        d_tmp1[65536 + gw] = a2 + bb;  d_tmp1[98304 + gw] = a3 + bb;
    }
}

// ---------------- 3. per-gate bias ----------------
__global__ void k_bias(const float* __restrict__ meta, const float* __restrict__ blw,
                       const float* __restrict__ blb) {
    int gw = (blockIdx.x * 256 + threadIdx.x) >> 5;
    int lane = threadIdx.x & 31;
    int b = gw >> 8, o = gw & 255;
    const float* row = blw + o * 256;
    const float* m = meta + b * 256;
    float a = 0.f;
    for (int k = lane; k < 256; k += 32) a += row[k] * m[k];
    #pragma unroll
    for (int s = 16; s > 0; s >>= 1) a += __shfl_xor_sync(~0u, a, s);
    if (lane == 0) d_bm[gw] = a + blb[o];
}

// ---------------- 4. hyper stage 2: GEMM 512x2304x256 -> scatter A[b][o][c*9+n] (hi/lo) ----------------
__global__ __launch_bounds__(256) void k_hyper2(const float* __restrict__ w2w,
                                                const float* __restrict__ w2b) {
    __shared__ float As[16][68];
    __shared__ float Bs[16][132];
    int tid = threadIdx.x;
    int row0 = blockIdx.y * 64;      // (b,c) rows, 512
    int col0 = blockIdx.x * 128;     // j cols, 2304
    int ty = tid >> 4, tx = tid & 15;
    float acc[4][8] = {};
    for (int k0 = 0; k0 < 256; k0 += 16) {
        {
            int r = tid >> 2, kk4 = (tid & 3) << 2;
            float4 va = *(const float4*)(d_tmp1 + (size_t)(row0 + r) * 256 + k0 + kk4);
            As[kk4 + 0][r] = va.x; As[kk4 + 1][r] = va.y;
            As[kk4 + 2][r] = va.z; As[kk4 + 3][r] = va.w;
        }
        #pragma unroll
        for (int i = 0; i < 2; i++) {
            int l = tid + i * 256;
            int r = l >> 2, kk4 = (l & 3) << 2;
            float4 vb = *(const float4*)(w2w + (size_t)(col0 + r) * 256 + k0 + kk4);
            Bs[kk4 + 0][r] = vb.x; Bs[kk4 + 1][r] = vb.y;
            Bs[kk4 + 2][r] = vb.z; Bs[kk4 + 3][r] = vb.w;
        }
        __syncthreads();
        #pragma unroll
        for (int kk = 0; kk < 16; kk++) {
            float ra[4], rb[8];
            #pragma unroll
            for (int i = 0; i < 4; i++) ra[i] = As[kk][ty * 4 + i];
            #pragma unroll
            for (int j = 0; j < 8; j++) rb[j] = Bs[kk][tx * 8 + j];
            #pragma unroll
            for (int i = 0; i < 4; i++)
                #pragma unroll
                for (int j = 0; j < 8; j++) acc[i][j] += ra[i] * rb[j];
        }
        __syncthreads();
    }
    #pragma unroll
    for (int i = 0; i < 4; i++) {
        int gr = row0 + ty * 4 + i;
        int b = gr >> 7, c = gr & 127;
        #pragma unroll
        for (int j = 0; j < 8; j++) {
            int jj = col0 + tx * 8 + j;
            int o = jj / 9, n = jj - o * 9;
            d_Ao2[((size_t)(b * 256 + o)) * CN + c * 9 + n] = split_tf32(acc[i][j] + w2b[jj]);
        }
    }
}

// ---------------- 5. offset conv + positions/weights ----------------
__global__ void k_offset(const float* __restrict__ mio, const float* __restrict__ pw,
                         const float* __restrict__ pb) {
    __shared__ float sw[162];
    __shared__ float sb[18];
    if (threadIdx.x < 162) sw[threadIdx.x] = pw[threadIdx.x];
    if (threadIdx.x < 18)  sb[threadIdx.x] = pb[threadIdx.x];
    __syncthreads();
    int b = blockIdx.y;
    int hw = blockIdx.x * 256 + threadIdx.x;
    int h = hw >> 6, w = hw & 63;
    const float* plane = mio + b * 4096;
    float v[9];
    #pragma unroll
    for (int kh = 0; kh < 3; kh++)
        #pragma unroll
        for (int kw = 0; kw < 3; kw++) {
            int hi = h - 1 + kh, wi = w - 1 + kw;
            v[kh * 3 + kw] = (hi >= 0 && hi < 64 && wi >= 0 && wi < 64) ? plane[hi * 64 + wi] : 0.f;
        }
    #pragma unroll
    for (int n = 0; n < 9; n++) {
        float offx = sb[n], offy = sb[9 + n];
        #pragma unroll
        for (int t = 0; t < 9; t++) {
            offx += v[t] * sw[n * 9 + t];
            offy += v[t] * sw[(9 + n) * 9 + t];
        }
        float px = (float)(h + 1) + (float)(n / 3 - 1) + offx;
        float py = (float)(w + 1) + (float)(n % 3 - 1) + offy;
        float fx = floorf(px), fy = floorf(py);
        int xlt = min(max((int)fx, 0), 65);
        int xrb = min(max((int)fx + 1, 0), 65);
        int ylt = min(max((int)fy, 0), 65);
        int yrb = min(max((int)fy + 1, 0), 65);
        float pcx = fminf(fmaxf(px, 0.f), 65.f);
        float pcy = fminf(fmaxf(py, 0.f), 65.f);
        float glt = (1.f + ((float)xlt - pcx)) * (1.f + ((float)ylt - pcy));
        float grb = (1.f - ((float)xrb - pcx)) * (1.f - ((float)yrb - pcy));
        float glb = (1.f + ((float)xlt - pcx)) * (1.f - ((float)yrb - pcy));
        float grt = (1.f - ((float)xrb - pcx)) * (1.f + ((float)ylt - pcy));
        int base = ((b * 9 + n) * HW4 + hw) * 4;
        *(int4*)(d_idx + base) = make_int4(xlt * 66 + ylt, xrb * 66 + yrb,
                                           xlt * 66 + yrb, xrb * 66 + ylt);
        *(float4*)(d_gw + base) = make_float4(glt, grb, glb, grt);
    }
}

// ---------------- 6. fused gather + transpose: x_offT[b][hw][k] hi/lo ----------------
__global__ __launch_bounds__(256) void k_sample_t() {
    extern __shared__ float2 smf2[];           // [16][1153] float2
    __shared__ int4   sidx[9][16];
    __shared__ float4 sg[9][16];
    int b = blockIdx.y;
    int hw0 = blockIdx.x * 16;
    int tid = threadIdx.x;
    if (tid < 144) {
        int n = tid / 16, hl = tid & 15;
        int base = ((b * 9 + n) * HW4 + hw0 + hl) * 4;
        sidx[n][hl] = *(const int4*)(d_idx + base);
        sg[n][hl]   = *(const float4*)(d_gw + base);
    }
    __syncthreads();
    int hl = tid & 15;
    int cbase = tid >> 4;                      // 0..15
    const float* xpb = d_xpad + (size_t)b * 128 * 4356;
    #pragma unroll
    for (int pass = 0; pass < 8; pass++) {
        int c = pass * 16 + cbase;
        const float* pl = xpb + c * 4356;
        float2* dst = smf2 + hl * 1153 + c * 9;
        #pragma unroll
        for (int n = 0; n < 9; n++) {
            int4 id = sidx[n][hl];
            float4 g = sg[n][hl];
            float val = g.x * pl[id.x] + g.y * pl[id.y] + g.z * pl[id.z] + g.w * pl[id.w];
            dst[n] = split_tf32(val);
        }
    }
    __syncthreads();
    float2* out = d_xoffT2 + (size_t)(b * HW4 + hw0) * CN;
    #pragma unroll
    for (int j = 0; j < 72; j++) {
        int lin = j * 256 + tid;               // < 18432
        int row = lin / CN, col = lin - row * CN;
        out[(size_t)row * CN + col] = smf2[row * 1153 + col];
    }
}

// ---------------- 7. main contraction via 3xTF32 mma.sync ----------------
// Per b: C[256 o][4096 hw] = Ao[256][1152] * xoffT[hw][1152]^T + bias.
// CTA: 256(m=o) x 64(n=hw), 8 warps (warp = 64m x 32n). kc=32, hi/lo interleaved.
// SMEM row = 32 k * float2 = 256B data, padded to 288B.
#define KC 32
#define RPAD 72                            // floats per row (36 float2)
#define ABYTES (256 * RPAD * 4)            // 73728
#define BBYTES (64 * RPAD * 4)             // 18432
#define STG (ABYTES + BBYTES)              // 92160

__global__ __launch_bounds__(256, 1) void k_gemm_mma() {
    extern __shared__ char smb[];
    uint32_t s0 = smem_u32(smb);
    int tid = threadIdx.x, wid = tid >> 5, lane = tid & 31;
    int b = blockIdx.y;
    int hw0 = blockIdx.x * 64;

    const float2* Abase = d_Ao2 + (size_t)b * 256 * CN;
    const float2* Bbase = d_xoffT2 + (size_t)(b * HW4 + hw0) * CN;

    auto load_stage = [&](int stage, int k0) {
        uint32_t sa = s0 + stage * STG;
        #pragma unroll
        for (int i = 0; i < 16; i++) {
            int l = tid + i * 256;
            int r = l >> 4, seg = l & 15;          // 16 x 16B chunks per row (2 float2 each)
            CP_ASYNC16(sa + r * (RPAD * 4) + seg * 16,
                       Abase + (size_t)r * CN + k0 + seg * 2);
        }
        uint32_t sbB = sa + ABYTES;
        #pragma unroll
        for (int i = 0; i < 4; i++) {
            int l = tid + i * 256;
            int r = l >> 4, seg = l & 15;
            CP_ASYNC16(sbB + r * (RPAD * 4) + seg * 16,
                       Bbase + (size_t)r * CN + k0 + seg * 2);
        }
    };

    float acc[4][4][4];
    #pragma unroll
    for (int i = 0; i < 4; i++)
        #pragma unroll
        for (int j = 0; j < 4; j++)
            #pragma unroll
            for (int q = 0; q < 4; q++) acc[i][j][q] = 0.f;

    load_stage(0, 0);
    CP_COMMIT();

    int m0 = (wid >> 1) * 64 + (lane >> 2);
    int n0 = (wid & 1) * 32 + (lane >> 2);
    int kq = lane & 3;

    for (int it = 0; it < 36; it++) {
        int cur = it & 1;
        if (it + 1 < 36) {
            load_stage(1 - cur, (it + 1) * KC);
            CP_COMMIT();
            CP_WAIT(1);
        } else {
            CP_WAIT(0);
        }
        __syncthreads();
        const float* As = (const float*)(smb + cur * STG);
        const float* Bs = (const float*)(smb + cur * STG + ABYTES);
        #pragma unroll
        for (int k8 = 0; k8 < 4; k8++) {
            int k = k8 * 8 + kq;
            uint32_t ah[4][4], al[4][4];
            #pragma unroll
            for (int mt = 0; mt < 4; mt++) {
                const float* Ap = As + (m0 + mt * 16) * RPAD;
                float2 f0 = *(const float2*)(Ap + 2 * k);
                float2 f1 = *(const float2*)(Ap + 8 * RPAD + 2 * k);
                float2 f2 = *(const float2*)(Ap + 2 * (k + 4));
                float2 f3 = *(const float2*)(Ap + 8 * RPAD + 2 * (k + 4));
                ah[mt][0] = __float_as_uint(f0.x); al[mt][0] = __float_as_uint(f0.y);
                ah[mt][1] = __float_as_uint(f1.x); al[mt][1] = __float_as_uint(f1.y);
                ah[mt][2] = __float_as_uint(f2.x); al[mt][2] = __float_as_uint(f2.y);
                ah[mt][3] = __float_as_uint(f3.x); al[mt][3] = __float_as_uint(f3.y);
            }
            uint32_t bh[4][2], bl[4][2];
            #pragma unroll
            for (int nt = 0; nt < 4; nt++) {
                const float* Bp = Bs + (n0 + nt * 8) * RPAD;
                float2 f0 = *(const float2*)(Bp + 2 * k);
                float2 f1 = *(const float2*)(Bp + 2 * (k + 4));
                bh[nt][0] = __float_as_uint(f0.x); bl[nt][0] = __float_as_uint(f0.y);
                bh[nt][1] = __float_as_uint(f1.x); bl[nt][1] = __float_as_uint(f1.y);
            }
            #pragma unroll
            for (int mt = 0; mt < 4; mt++)
                #pragma unroll
                for (int nt = 0; nt < 4; nt++) {
                    mma_tf32(acc[mt][nt], ah[mt], bh[nt]);
                    mma_tf32(acc[mt][nt], ah[mt], bl[nt]);
                    mma_tf32(acc[mt][nt], al[mt], bh[nt]);
                }
        }
        __syncthreads();
    }

    // epilogue: C[o][hw] += bias[o]
    float* Cg = d_comb + (size_t)b * 256 * HW4;
    const float* bmp = d_bm + b * 256;
    int mwarp = (wid >> 1) * 64;
    int nwarp = (wid & 1) * 32;
    #pragma unroll
    for (int mt = 0; mt < 4; mt++) {
        int row = mwarp + mt * 16 + (lane >> 2);
        float bz0 = bmp[row], bz1 = bmp[row + 8];
        #pragma unroll
        for (int nt = 0; nt < 4; nt++) {
            int col = hw0 + nwarp + nt * 8 + (lane & 3) * 2;
            float2 v0 = make_float2(acc[mt][nt][0] + bz0, acc[mt][nt][1] + bz0);
            float2 v1 = make_float2(acc[mt][nt][2] + bz1, acc[mt][nt][3] + bz1);
            *(float2*)(Cg + (size_t)row * HW4 + col) = v0;
            *(float2*)(Cg + (size_t)(row + 8) * HW4 + col) = v1;
        }
    }
}

// ---------------- 8. LSTM gates ----------------
__global__ void k_gates(const float* __restrict__ ccur, float* __restrict__ out) {
    int i = blockIdx.x * 256 + threadIdx.x;
    int b = i >> 18;
    int r = i & 262143;
    int hid = r >> 12, hw = r & 4095;
    const float* cb = d_comb + (size_t)b * 256 * HW4;
    float ci = cb[(size_t)(hid)       * HW4 + hw];
    float cf = cb[(size_t)(hid + 64)  * HW4 + hw];
    float co = cb[(size_t)(hid + 128) * HW4 + hw];
    float cg = cb[(size_t)(hid + 192) * HW4 + hw];
    float ig = 1.f / (1.f + expf(-ci));
    float fg = 1.f / (1.f + expf(-cf));
    float og = 1.f / (1.f + expf(-co));
    float gg = tanhf(cg);
    float cn = fg * ccur[i] + ig * gg;
    float hn = og * tanhf(cn);
    out[i] = hn;
    out[1048576 + i] = cn;
}

// ---------------- launch ----------------
extern "C" void kernel_launch(void* const* d_in, const int* in_sizes, int n_in,
                              void* d_out, int out_size) {
    const float* inp  = (const float*)d_in[0];
    const float* hcur = (const float*)d_in[1];
    const float* ccur = (const float*)d_in[2];
    const float* meta = (const float*)d_in[3];
    const float* mio  = (const float*)d_in[4];
    const float* w1w  = (const float*)d_in[5];
    const float* w1b  = (const float*)d_in[6];
    const float* w2w  = (const float*)d_in[7];
    const float* w2b  = (const float*)d_in[8];
    const float* blw  = (const float*)d_in[9];
    const float* blb  = (const float*)d_in[10];
    const float* pw   = (const float*)d_in[11];
    const float* pb   = (const float*)d_in[12];
    float* out = (float*)d_out;

    cudaFuncSetAttribute(k_sample_t, cudaFuncAttributeMaxDynamicSharedMemorySize, 16 * 1153 * 8);
    cudaFuncSetAttribute(k_gemm_mma, cudaFuncAttributeMaxDynamicSharedMemorySize, 2 * STG);

    k_pad     <<<8712, 256>>>(inp, hcur);
    k_w1      <<<4096, 256>>>(meta, w1w, w1b);
    k_bias    <<<128, 256>>>(meta, blw, blb);
    k_hyper2  <<<dim3(18, 8), 256>>>(w2w, w2b);
    k_offset  <<<dim3(16, 4), 256>>>(mio, pw, pb);
    k_sample_t<<<dim3(256, 4), 256, 16 * 1153 * 8>>>();
    k_gemm_mma<<<dim3(64, 4), 256, 2 * STG>>>();
    k_gates   <<<4096, 256>>>(ccur, out);
}

// round 6
// speedup vs baseline: 2.1421x; 2.1421x over previous
#include <cuda_runtime.h>
#include <cuda_bf16.h>
#include <math.h>
#include <stdint.h>

// B=4, CIN=64, HID=64, H=W=64, K=3, N=9, D=256, INC=128, OUTC=256
// HP=WP=66, HW=4096, CN = INC*9 = 1152
#define HW4 4096
#define CN 1152

// ---------------- scratch ----------------
__device__ float          d_tmp1[4 * 128 * 256];            // [b][c][d]
__device__ __nv_bfloat16  d_Ahi[4 * 256 * CN];              // [b][o][k] bf16 hi
__device__ __nv_bfloat16  d_Alo[4 * 256 * CN];              // [b][o][k] bf16 lo
__device__ float          d_bm[4 * 256];                    // [b][o]
__device__ int            d_idx[4 * 9 * HW4 * 4];           // [b][n][hw][4]
__device__ float          d_gw [4 * 9 * HW4 * 4];           // [b][n][hw][4]
__device__ float          d_xpad[4 * 128 * 66 * 66];        // [b][c][66][66]
__device__ __nv_bfloat16  d_Bhi[(size_t)4 * HW4 * CN];      // [b][hw][k] bf16 hi  37.7MB
__device__ __nv_bfloat16  d_Blo[(size_t)4 * HW4 * CN];      // [b][hw][k] bf16 lo  37.7MB

// ---------------- helpers ----------------
__device__ __forceinline__ uint32_t smem_u32(const void* p) {
    uint32_t a;
    asm("{ .reg .u64 t; cvta.to.shared.u64 t, %1; cvt.u32.u64 %0, t; }" : "=r"(a) : "l"(p));
    return a;
}
#define CP_ASYNC16(dst, src) asm volatile("cp.async.cg.shared.global [%0], [%1], 16;" :: "r"(dst), "l"(src))
#define CP_COMMIT()          asm volatile("cp.async.commit_group;" ::: "memory")
#define CP_WAIT(n)           asm volatile("cp.async.wait_group %0;" :: "n"(n) : "memory")

__device__ __forceinline__ void mma_bf16(float* c, const uint32_t* a, const uint32_t* b) {
    asm volatile(
        "mma.sync.aligned.m16n8k16.row.col.f32.bf16.bf16.f32 "
        "{%0,%1,%2,%3}, {%4,%5,%6,%7}, {%8,%9}, {%0,%1,%2,%3};"
        : "+f"(c[0]), "+f"(c[1]), "+f"(c[2]), "+f"(c[3])
        : "r"(a[0]), "r"(a[1]), "r"(a[2]), "r"(a[3]), "r"(b[0]), "r"(b[1]));
}

__device__ __forceinline__ void split_bf16(float v, __nv_bfloat16& hi, __nv_bfloat16& lo) {
    hi = __float2bfloat16(v);
    lo = __float2bfloat16(v - __bfloat162float(hi));
}

// ---------------- 1. concat + ZeroPad2d(1) ----------------
__global__ void k_pad(const float* __restrict__ inp, const float* __restrict__ hcur) {
    int i = blockIdx.x * 256 + threadIdx.x;
    const int total = 4 * 128 * 66 * 66;
    if (i >= total) return;
    int wp = i % 66;
    int t = i / 66;
    int hp = t % 66; t /= 66;
    int c = t % 128; int b = t / 128;
    float v = 0.f;
    if (hp >= 1 && hp <= 64 && wp >= 1 && wp <= 64) {
        int sp = ((b * 64 + (c < 64 ? c : c - 64)) * 64 + (hp - 1)) * 64 + (wp - 1);
        v = (c < 64) ? inp[sp] : hcur[sp];
    }
    d_xpad[i] = v;
}

// ---------------- 2. hyper stage 1 ----------------
__global__ void k_w1(const float* __restrict__ meta, const float* __restrict__ w1w,
                     const float* __restrict__ w1b) {
    __shared__ float sm[1024];
    for (int i = threadIdx.x; i < 1024; i += 256) sm[i] = meta[i];
    __syncthreads();
    int gw = (blockIdx.x * 256 + threadIdx.x) >> 5;
    int lane = threadIdx.x & 31;
    const float* row = w1w + (size_t)gw * 256;
    float a0 = 0.f, a1 = 0.f, a2 = 0.f, a3 = 0.f;
    #pragma unroll
    for (int k = lane; k < 256; k += 32) {
        float wv = row[k];
        a0 += wv * sm[k];       a1 += wv * sm[256 + k];
        a2 += wv * sm[512 + k]; a3 += wv * sm[768 + k];
    }
    #pragma unroll
    for (int s = 16; s > 0; s >>= 1) {
        a0 += __shfl_xor_sync(~0u, a0, s); a1 += __shfl_xor_sync(~0u, a1, s);
        a2 += __shfl_xor_sync(~0u, a2, s); a3 += __shfl_xor_sync(~0u, a3, s);
    }
    if (lane == 0) {
        float bb = w1b[gw];
        d_tmp1[gw] = a0 + bb;          d_tmp1[32768 + gw] = a1 + bb;
        d_tmp1[65536 + gw] = a2 + bb;  d_tmp1[98304 + gw] = a3 + bb;
    }
}

// ---------------- 3. per-gate bias ----------------
__global__ void k_bias(const float* __restrict__ meta, const float* __restrict__ blw,
                       const float* __restrict__ blb) {
    int gw = (blockIdx.x * 256 + threadIdx.x) >> 5;
    int lane = threadIdx.x & 31;
    int b = gw >> 8, o = gw & 255;
    const float* row = blw + o * 256;
    const float* m = meta + b * 256;
    float a = 0.f;
    for (int k = lane; k < 256; k += 32) a += row[k] * m[k];
    #pragma unroll
    for (int s = 16; s > 0; s >>= 1) a += __shfl_xor_sync(~0u, a, s);
    if (lane == 0) d_bm[gw] = a + blb[o];
}

// ---------------- 4. hyper stage 2: GEMM 512x2304x256 -> A hi/lo bf16 [b][o][c*9+n] ----------------
__global__ __launch_bounds__(256) void k_hyper2(const float* __restrict__ w2w,
                                                const float* __restrict__ w2b) {
    __shared__ float As[16][68];
    __shared__ float Bs[16][68];
    int tid = threadIdx.x;
    int row0 = blockIdx.y * 64;      // (b,c) rows, 512
    int col0 = blockIdx.x * 64;      // j cols, 2304
    int ty = tid >> 4, tx = tid & 15;
    float acc[4][4] = {};
    for (int k0 = 0; k0 < 256; k0 += 16) {
        {
            int r = tid >> 2, kk4 = (tid & 3) << 2;
            float4 va = *(const float4*)(d_tmp1 + (size_t)(row0 + r) * 256 + k0 + kk4);
            As[kk4 + 0][r] = va.x; As[kk4 + 1][r] = va.y;
            As[kk4 + 2][r] = va.z; As[kk4 + 3][r] = va.w;
            float4 vb = *(const float4*)(w2w + (size_t)(col0 + r) * 256 + k0 + kk4);
            Bs[kk4 + 0][r] = vb.x; Bs[kk4 + 1][r] = vb.y;
            Bs[kk4 + 2][r] = vb.z; Bs[kk4 + 3][r] = vb.w;
        }
        __syncthreads();
        #pragma unroll
        for (int kk = 0; kk < 16; kk++) {
            float ra[4], rb[4];
            #pragma unroll
            for (int i = 0; i < 4; i++) ra[i] = As[kk][ty * 4 + i];
            #pragma unroll
            for (int j = 0; j < 4; j++) rb[j] = Bs[kk][tx * 4 + j];
            #pragma unroll
            for (int i = 0; i < 4; i++)
                #pragma unroll
                for (int j = 0; j < 4; j++) acc[i][j] += ra[i] * rb[j];
        }
        __syncthreads();
    }
    #pragma unroll
    for (int i = 0; i < 4; i++) {
        int gr = row0 + ty * 4 + i;
        int b = gr >> 7, c = gr & 127;
        #pragma unroll
        for (int j = 0; j < 4; j++) {
            int jj = col0 + tx * 4 + j;
            int o = jj / 9, n = jj - o * 9;
            size_t dst = ((size_t)(b * 256 + o)) * CN + c * 9 + n;
            __nv_bfloat16 hi, lo;
            split_bf16(acc[i][j] + w2b[jj], hi, lo);
            d_Ahi[dst] = hi;
            d_Alo[dst] = lo;
        }
    }
}

// ---------------- 5. offset conv + positions/weights ----------------
__global__ void k_offset(const float* __restrict__ mio, const float* __restrict__ pw,
                         const float* __restrict__ pb) {
    __shared__ float sw[162];
    __shared__ float sb[18];
    if (threadIdx.x < 162) sw[threadIdx.x] = pw[threadIdx.x];
    if (threadIdx.x < 18)  sb[threadIdx.x] = pb[threadIdx.x];
    __syncthreads();
    int b = blockIdx.y;
    int hw = blockIdx.x * 256 + threadIdx.x;
    int h = hw >> 6, w = hw & 63;
    const float* plane = mio + b * 4096;
    float v[9];
    #pragma unroll
    for (int kh = 0; kh < 3; kh++)
        #pragma unroll
        for (int kw = 0; kw < 3; kw++) {
            int hi = h - 1 + kh, wi = w - 1 + kw;
            v[kh * 3 + kw] = (hi >= 0 && hi < 64 && wi >= 0 && wi < 64) ? plane[hi * 64 + wi] : 0.f;
        }
    #pragma unroll
    for (int n = 0; n < 9; n++) {
        float offx = sb[n], offy = sb[9 + n];
        #pragma unroll
        for (int t = 0; t < 9; t++) {
            offx += v[t] * sw[n * 9 + t];
            offy += v[t] * sw[(9 + n) * 9 + t];
        }
        float px = (float)(h + 1) + (float)(n / 3 - 1) + offx;
        float py = (float)(w + 1) + (float)(n % 3 - 1) + offy;
        float fx = floorf(px), fy = floorf(py);
        int xlt = min(max((int)fx, 0), 65);
        int xrb = min(max((int)fx + 1, 0), 65);
        int ylt = min(max((int)fy, 0), 65);
        int yrb = min(max((int)fy + 1, 0), 65);
        float pcx = fminf(fmaxf(px, 0.f), 65.f);
        float pcy = fminf(fmaxf(py, 0.f), 65.f);
        float glt = (1.f + ((float)xlt - pcx)) * (1.f + ((float)ylt - pcy));
        float grb = (1.f - ((float)xrb - pcx)) * (1.f - ((float)yrb - pcy));
        float glb = (1.f + ((float)xlt - pcx)) * (1.f - ((float)yrb - pcy));
        float grt = (1.f - ((float)xrb - pcx)) * (1.f + ((float)ylt - pcy));
        int base = ((b * 9 + n) * HW4 + hw) * 4;
        *(int4*)(d_idx + base) = make_int4(xlt * 66 + ylt, xrb * 66 + yrb,
                                           xlt * 66 + yrb, xrb * 66 + ylt);
        *(float4*)(d_gw + base) = make_float4(glt, grb, glb, grt);
    }
}

// ---------------- 6. fused gather + transpose + bf16 split: [b][hw][k] ----------------
#define SPITCH 1160          // bf16 pitch per hw row in smem (even)
__global__ __launch_bounds__(256) void k_sample_t() {
    extern __shared__ __nv_bfloat16 smbf[];    // hi [16][1160], lo [16][1160]
    __nv_bfloat16* shi = smbf;
    __nv_bfloat16* slo = smbf + 16 * SPITCH;
    __shared__ int4   sidx[9][16];
    __shared__ float4 sg[9][16];
    int b = blockIdx.y;
    int hw0 = blockIdx.x * 16;
    int tid = threadIdx.x;
    if (tid < 144) {
        int n = tid / 16, hl = tid & 15;
        int base = ((b * 9 + n) * HW4 + hw0 + hl) * 4;
        sidx[n][hl] = *(const int4*)(d_idx + base);
        sg[n][hl]   = *(const float4*)(d_gw + base);
    }
    __syncthreads();
    int hl = tid & 15;
    int cbase = tid >> 4;                      // 0..15
    const float* xpb = d_xpad + (size_t)b * 128 * 4356;
    #pragma unroll
    for (int pass = 0; pass < 8; pass++) {
        int c = pass * 16 + cbase;
        const float* pl = xpb + c * 4356;
        int dbase = hl * SPITCH + c * 9;
        #pragma unroll
        for (int n = 0; n < 9; n++) {
            int4 id = sidx[n][hl];
            float4 g = sg[n][hl];
            float val = g.x * pl[id.x] + g.y * pl[id.y] + g.z * pl[id.z] + g.w * pl[id.w];
            __nv_bfloat16 hi, lo;
            split_bf16(val, hi, lo);
            shi[dbase + n] = hi;
            slo[dbase + n] = lo;
        }
    }
    __syncthreads();
    const uint32_t* shi32 = (const uint32_t*)shi;
    const uint32_t* slo32 = (const uint32_t*)slo;
    uint32_t* ohi = (uint32_t*)d_Bhi + (size_t)(b * HW4 + hw0) * (CN / 2);
    uint32_t* olo = (uint32_t*)d_Blo + (size_t)(b * HW4 + hw0) * (CN / 2);
    #pragma unroll
    for (int j = 0; j < 36; j++) {
        int lin = j * 256 + tid;               // < 9216
        int row = lin / 576, col = lin - row * 576;
        ohi[(size_t)row * 576 + col] = shi32[row * (SPITCH / 2) + col];
        olo[(size_t)row * 576 + col] = slo32[row * (SPITCH / 2) + col];
    }
}

// ---------------- 7. main contraction: bf16x3 mma.sync + fused LSTM gates ----------------
// Per b: C[256 o][64 hw tile] = A[256][1152] * B[hw][1152]^T + bias -> gates -> out.
// CTA: 256(m) x 64(n), 8 warps (warp 64m x 32n). kc=32 (2 x k16 steps), double-buffered.
// APITCH=40 bf16 (80B) -> 16B-aligned cp.async rows, conflict-free frag LDS (stride 20 words).
#define KC 32
#define APITCH 40                          // bf16 per smem row (80 bytes)
#define AHB (256 * APITCH * 2)             // 20480 bytes per A component
#define BHB (64 * APITCH * 2)              // 5120 bytes per B component
#define STG (2 * AHB + 2 * BHB)            // 51200
// stage offsets: AH=0, AL=AHB, BH=2*AHB, BL=2*AHB+BHB

__global__ __launch_bounds__(256, 1) void k_gemm_mma(const float* __restrict__ ccur,
                                                     float* __restrict__ out) {
    extern __shared__ char smb[];
    uint32_t s0 = smem_u32(smb);
    int tid = threadIdx.x, wid = tid >> 5, lane = tid & 31;
    int b = blockIdx.y;
    int hw0 = blockIdx.x * 64;

    const __nv_bfloat16* Ahi = d_Ahi + (size_t)b * 256 * CN;
    const __nv_bfloat16* Alo = d_Alo + (size_t)b * 256 * CN;
    const __nv_bfloat16* Bhi = d_Bhi + (size_t)(b * HW4 + hw0) * CN;
    const __nv_bfloat16* Blo = d_Blo + (size_t)(b * HW4 + hw0) * CN;

    auto load_stage = [&](int stage, int k0) {
        uint32_t sa = s0 + stage * STG;
        // A hi/lo: 256 rows x 64B (32 bf16) = 4 x 16B chunks per row
        #pragma unroll
        for (int i = 0; i < 4; i++) {
            int l = tid + i * 256;
            int r = l >> 2, seg = l & 3;
            CP_ASYNC16(sa + r * (APITCH * 2) + seg * 16,
                       Ahi + (size_t)r * CN + k0 + seg * 8);
        }
        #pragma unroll
        for (int i = 0; i < 4; i++) {
            int l = tid + i * 256;
            int r = l >> 2, seg = l & 3;
            CP_ASYNC16(sa + AHB + r * (APITCH * 2) + seg * 16,
                       Alo + (size_t)r * CN + k0 + seg * 8);
        }
        // B hi/lo: 64 rows x 4 chunks
        {
            int r = tid >> 2, seg = tid & 3;
            CP_ASYNC16(sa + 2 * AHB + r * (APITCH * 2) + seg * 16,
                       Bhi + (size_t)r * CN + k0 + seg * 8);
            CP_ASYNC16(sa + 2 * AHB + BHB + r * (APITCH * 2) + seg * 16,
                       Blo + (size_t)r * CN + k0 + seg * 8);
        }
    };

    float acc[4][4][4];
    #pragma unroll
    for (int i = 0; i < 4; i++)
        #pragma unroll
        for (int j = 0; j < 4; j++)
            #pragma unroll
            for (int q = 0; q < 4; q++) acc[i][j][q] = 0.f;

    load_stage(0, 0);
    CP_COMMIT();

    int mwarp = (wid >> 1) * 64;
    int nwarp = (wid & 1) * 32;
    int grp = lane >> 2;                   // 0..7
    int tig = lane & 3;                    // 0..3
    int m0 = mwarp + grp;
    int n0 = nwarp + grp;

    for (int it = 0; it < 36; it++) {
        int cur = it & 1;
        if (it + 1 < 36) {
            load_stage(1 - cur, (it + 1) * KC);
            CP_COMMIT();
            CP_WAIT(1);
        } else {
            CP_WAIT(0);
        }
        __syncthreads();
        const __nv_bfloat16* AH = (const __nv_bfloat16*)(smb + cur * STG);
        const __nv_bfloat16* AL = (const __nv_bfloat16*)(smb + cur * STG + AHB);
        const __nv_bfloat16* BH = (const __nv_bfloat16*)(smb + cur * STG + 2 * AHB);
        const __nv_bfloat16* BL = (const __nv_bfloat16*)(smb + cur * STG + 2 * AHB + BHB);
        #pragma unroll
        for (int s = 0; s < 2; s++) {
            int kb = s * 16 + 2 * tig;
            uint32_t ah[4][4], al[4][4];
            #pragma unroll
            for (int mt = 0; mt < 4; mt++) {
                int r = m0 + mt * 16;
                ah[mt][0] = *(const uint32_t*)(AH + r * APITCH + kb);
                ah[mt][1] = *(const uint32_t*)(AH + (r + 8) * APITCH + kb);
                ah[mt][2] = *(const uint32_t*)(AH + r * APITCH + kb + 8);
                ah[mt][3] = *(const uint32_t*)(AH + (r + 8) * APITCH + kb + 8);
                al[mt][0] = *(const uint32_t*)(AL + r * APITCH + kb);
                al[mt][1] = *(const uint32_t*)(AL + (r + 8) * APITCH + kb);
                al[mt][2] = *(const uint32_t*)(AL + r * APITCH + kb + 8);
                al[mt][3] = *(const uint32_t*)(AL + (r + 8) * APITCH + kb + 8);
            }
            uint32_t bh[4][2], bl[4][2];
            #pragma unroll
            for (int nt = 0; nt < 4; nt++) {
                int r = n0 + nt * 8;
                bh[nt][0] = *(const uint32_t*)(BH + r * APITCH + kb);
                bh[nt][1] = *(const uint32_t*)(BH + r * APITCH + kb + 8);
                bl[nt][0] = *(const uint32_t*)(BL + r * APITCH + kb);
                bl[nt][1] = *(const uint32_t*)(BL + r * APITCH + kb + 8);
            }
            #pragma unroll
            for (int mt = 0; mt < 4; mt++)
                #pragma unroll
                for (int nt = 0; nt < 4; nt++) {
                    mma_bf16(acc[mt][nt], ah[mt], bh[nt]);
                    mma_bf16(acc[mt][nt], ah[mt], bl[nt]);
                    mma_bf16(acc[mt][nt], al[mt], bh[nt]);
                }
        }
        __syncthreads();
    }

    // ---- stage C tile (with bias) into smem, then fused LSTM gates ----
    __syncthreads();
    float* Cs = (float*)smb;               // [256][68] = 69632 bytes < 2*STG
    const float* bmp = d_bm + b * 256;
    #pragma unroll
    for (int mt = 0; mt < 4; mt++) {
        int row = mwarp + mt * 16 + grp;
        float bz0 = bmp[row], bz1 = bmp[row + 8];
        #pragma unroll
        for (int nt = 0; nt < 4; nt++) {
            int col = nwarp + nt * 8 + tig * 2;
            Cs[row * 68 + col]           = acc[mt][nt][0] + bz0;
            Cs[row * 68 + col + 1]       = acc[mt][nt][1] + bz0;
            Cs[(row + 8) * 68 + col]     = acc[mt][nt][2] + bz1;
            Cs[(row + 8) * 68 + col + 1] = acc[mt][nt][3] + bz1;
        }
    }
    __syncthreads();
    #pragma unroll
    for (int q = 0; q < 16; q++) {
        int lin = q * 256 + tid;           // < 4096
        int hid = lin >> 6, hw = lin & 63;
        float ci = Cs[hid * 68 + hw];
        float cf = Cs[(hid + 64) * 68 + hw];
        float co = Cs[(hid + 128) * 68 + hw];
        float cg = Cs[(hid + 192) * 68 + hw];
        float ig = 1.f / (1.f + expf(-ci));
        float fg = 1.f / (1.f + expf(-cf));
        float og = 1.f / (1.f + expf(-co));
        float gg = tanhf(cg);
        int g = (b * 64 + hid) * HW4 + hw0 + hw;
        float cn = fg * ccur[g] + ig * gg;
        float hn = og * tanhf(cn);
        out[g] = hn;
        out[1048576 + g] = cn;
    }
}

// ---------------- launch ----------------
extern "C" void kernel_launch(void* const* d_in, const int* in_sizes, int n_in,
                              void* d_out, int out_size) {
    const float* inp  = (const float*)d_in[0];
    const float* hcur = (const float*)d_in[1];
    const float* ccur = (const float*)d_in[2];
    const float* meta = (const float*)d_in[3];
    const float* mio  = (const float*)d_in[4];
    const float* w1w  = (const float*)d_in[5];
    const float* w1b  = (const float*)d_in[6];
    const float* w2w  = (const float*)d_in[7];
    const float* w2b  = (const float*)d_in[8];
    const float* blw  = (const float*)d_in[9];
    const float* blb  = (const float*)d_in[10];
    const float* pw   = (const float*)d_in[11];
    const float* pb   = (const float*)d_in[12];
    float* out = (float*)d_out;

    cudaFuncSetAttribute(k_sample_t, cudaFuncAttributeMaxDynamicSharedMemorySize,
                         2 * 16 * SPITCH * 2);
    cudaFuncSetAttribute(k_gemm_mma, cudaFuncAttributeMaxDynamicSharedMemorySize, 2 * STG);

    k_pad     <<<8712, 256>>>(inp, hcur);
    k_w1      <<<4096, 256>>>(meta, w1w, w1b);
    k_bias    <<<128, 256>>>(meta, blw, blb);
    k_hyper2  <<<dim3(36, 8), 256>>>(w2w, w2b);
    k_offset  <<<dim3(16, 4), 256>>>(mio, pw, pb);
    k_sample_t<<<dim3(256, 4), 256, 2 * 16 * SPITCH * 2>>>();
    k_gemm_mma<<<dim3(64, 4), 256, 2 * STG>>>(ccur, out);
}

// round 7
// speedup vs baseline: 2.3763x; 1.1093x over previous
#include <cuda_runtime.h>
#include <cuda_bf16.h>
#include <math.h>
#include <stdint.h>

// B=4, CIN=64, HID=64, H=W=64, K=3, N=9, D=256, INC=128, OUTC=256
// HP=WP=66, HW=4096, CN = INC*9 = 1152
#define HW4 4096
#define CN 1152

// ---------------- scratch ----------------
__device__ float          d_tmp1[4 * 128 * 256];            // [b][c][d]
__device__ __nv_bfloat16  d_Ahi[4 * 256 * CN];              // [b][o][k] bf16 hi
__device__ __nv_bfloat16  d_Alo[4 * 256 * CN];              // [b][o][k] bf16 lo
__device__ float          d_bm[4 * 256];                    // [b][o]
__device__ int            d_idx[4 * 9 * HW4 * 4];           // [b][n][hw][4]
__device__ float          d_gw [4 * 9 * HW4 * 4];           // [b][n][hw][4]
__device__ float          d_xpad[4 * 128 * 66 * 66];        // [b][c][66][66]
__device__ __nv_bfloat16  d_Bhi[(size_t)4 * HW4 * CN];      // [b][hw][k] bf16 hi  37.7MB
__device__ __nv_bfloat16  d_Blo[(size_t)4 * HW4 * CN];      // [b][hw][k] bf16 lo  37.7MB

// ---------------- helpers ----------------
__device__ __forceinline__ uint32_t smem_u32(const void* p) {
    uint32_t a;
    asm("{ .reg .u64 t; cvta.to.shared.u64 t, %1; cvt.u32.u64 %0, t; }" : "=r"(a) : "l"(p));
    return a;
}
#define CP_ASYNC16(dst, src) asm volatile("cp.async.cg.shared.global [%0], [%1], 16;" :: "r"(dst), "l"(src))
#define CP_COMMIT()          asm volatile("cp.async.commit_group;" ::: "memory")
#define CP_WAIT(n)           asm volatile("cp.async.wait_group %0;" :: "n"(n) : "memory")
#define LDSM_X4(R0,R1,R2,R3,ADDR) \
    asm volatile("ldmatrix.sync.aligned.m8n8.x4.shared.b16 {%0,%1,%2,%3}, [%4];" \
                 : "=r"(R0),"=r"(R1),"=r"(R2),"=r"(R3) : "r"(ADDR))
#define LDSM_X2(R0,R1,ADDR) \
    asm volatile("ldmatrix.sync.aligned.m8n8.x2.shared.b16 {%0,%1}, [%2];" \
                 : "=r"(R0),"=r"(R1) : "r"(ADDR))

__device__ __forceinline__ void mma_bf16(float* c, const uint32_t* a, const uint32_t* b) {
    asm volatile(
        "mma.sync.aligned.m16n8k16.row.col.f32.bf16.bf16.f32 "
        "{%0,%1,%2,%3}, {%4,%5,%6,%7}, {%8,%9}, {%0,%1,%2,%3};"
        : "+f"(c[0]), "+f"(c[1]), "+f"(c[2]), "+f"(c[3])
        : "r"(a[0]), "r"(a[1]), "r"(a[2]), "r"(a[3]), "r"(b[0]), "r"(b[1]));
}

__device__ __forceinline__ void split_bf16(float v, __nv_bfloat16& hi, __nv_bfloat16& lo) {
    hi = __float2bfloat16(v);
    lo = __float2bfloat16(v - __bfloat162float(hi));
}

// ---------------- 1. concat + ZeroPad2d(1) ----------------
__global__ void k_pad(const float* __restrict__ inp, const float* __restrict__ hcur) {
    int i = blockIdx.x * 256 + threadIdx.x;
    const int total = 4 * 128 * 66 * 66;
    if (i >= total) return;
    int wp = i % 66;
    int t = i / 66;
    int hp = t % 66; t /= 66;
    int c = t % 128; int b = t / 128;
    float v = 0.f;
    if (hp >= 1 && hp <= 64 && wp >= 1 && wp <= 64) {
        int sp = ((b * 64 + (c < 64 ? c : c - 64)) * 64 + (hp - 1)) * 64 + (wp - 1);
        v = (c < 64) ? inp[sp] : hcur[sp];
    }
    d_xpad[i] = v;
}

// ---------------- 2. hyper stage 1 ----------------
__global__ void k_w1(const float* __restrict__ meta, const float* __restrict__ w1w,
                     const float* __restrict__ w1b) {
    __shared__ float sm[1024];
    for (int i = threadIdx.x; i < 1024; i += 256) sm[i] = meta[i];
    __syncthreads();
    int gw = (blockIdx.x * 256 + threadIdx.x) >> 5;
    int lane = threadIdx.x & 31;
    const float* row = w1w + (size_t)gw * 256;
    float a0 = 0.f, a1 = 0.f, a2 = 0.f, a3 = 0.f;
    #pragma unroll
    for (int k = lane; k < 256; k += 32) {
        float wv = row[k];
        a0 += wv * sm[k];       a1 += wv * sm[256 + k];
        a2 += wv * sm[512 + k]; a3 += wv * sm[768 + k];
    }
    #pragma unroll
    for (int s = 16; s > 0; s >>= 1) {
        a0 += __shfl_xor_sync(~0u, a0, s); a1 += __shfl_xor_sync(~0u, a1, s);
        a2 += __shfl_xor_sync(~0u, a2, s); a3 += __shfl_xor_sync(~0u, a3, s);
    }
    if (lane == 0) {
        float bb = w1b[gw];
        d_tmp1[gw] = a0 + bb;          d_tmp1[32768 + gw] = a1 + bb;
        d_tmp1[65536 + gw] = a2 + bb;  d_tmp1[98304 + gw] = a3 + bb;
    }
}

// ---------------- 3. per-gate bias ----------------
__global__ void k_bias(const float* __restrict__ meta, const float* __restrict__ blw,
                       const float* __restrict__ blb) {
    int gw = (blockIdx.x * 256 + threadIdx.x) >> 5;
    int lane = threadIdx.x & 31;
    int b = gw >> 8, o = gw & 255;
    const float* row = blw + o * 256;
    const float* m = meta + b * 256;
    float a = 0.f;
    for (int k = lane; k < 256; k += 32) a += row[k] * m[k];
    #pragma unroll
    for (int s = 16; s > 0; s >>= 1) a += __shfl_xor_sync(~0u, a, s);
    if (lane == 0) d_bm[gw] = a + blb[o];
}

// ---------------- 4. hyper stage 2: GEMM 512x2304x256 -> A hi/lo bf16 [b][o][c*9+n] ----------------
// tile 128x64, 256 threads, 8x4 acc. grid (36, 4).
__global__ __launch_bounds__(256) void k_hyper2(const float* __restrict__ w2w,
                                                const float* __restrict__ w2b) {
    __shared__ float As[16][132];
    __shared__ float Bs[16][68];
    int tid = threadIdx.x;
    int row0 = blockIdx.y * 128;     // (b,c) rows, 512
    int col0 = blockIdx.x * 64;      // j cols, 2304
    int ty = tid >> 4, tx = tid & 15;
    float acc[8][4] = {};
    for (int k0 = 0; k0 < 256; k0 += 16) {
        #pragma unroll
        for (int i = 0; i < 2; i++) {
            int l = tid + i * 256;
            int r = l >> 2, kk4 = (l & 3) << 2;
            float4 va = *(const float4*)(d_tmp1 + (size_t)(row0 + r) * 256 + k0 + kk4);
            As[kk4 + 0][r] = va.x; As[kk4 + 1][r] = va.y;
            As[kk4 + 2][r] = va.z; As[kk4 + 3][r] = va.w;
        }
        {
            int r = tid >> 2, kk4 = (tid & 3) << 2;
            float4 vb = *(const float4*)(w2w + (size_t)(col0 + r) * 256 + k0 + kk4);
            Bs[kk4 + 0][r] = vb.x; Bs[kk4 + 1][r] = vb.y;
            Bs[kk4 + 2][r] = vb.z; Bs[kk4 + 3][r] = vb.w;
        }
        __syncthreads();
        #pragma unroll
        for (int kk = 0; kk < 16; kk++) {
            float ra[8], rb[4];
            *(float4*)(ra)     = *(const float4*)&As[kk][ty * 8];
            *(float4*)(ra + 4) = *(const float4*)&As[kk][ty * 8 + 4];
            *(float4*)(rb)     = *(const float4*)&Bs[kk][tx * 4];
            #pragma unroll
            for (int i = 0; i < 8; i++)
                #pragma unroll
                for (int j = 0; j < 4; j++) acc[i][j] += ra[i] * rb[j];
        }
        __syncthreads();
    }
    #pragma unroll
    for (int i = 0; i < 8; i++) {
        int gr = row0 + ty * 8 + i;
        int b = gr >> 7, c = gr & 127;
        #pragma unroll
        for (int j = 0; j < 4; j++) {
            int jj = col0 + tx * 4 + j;
            int o = jj / 9, n = jj - o * 9;
            size_t dst = ((size_t)(b * 256 + o)) * CN + c * 9 + n;
            __nv_bfloat16 hi, lo;
            split_bf16(acc[i][j] + w2b[jj], hi, lo);
            d_Ahi[dst] = hi;
            d_Alo[dst] = lo;
        }
    }
}

// ---------------- 5. offset conv + positions/weights ----------------
__global__ void k_offset(const float* __restrict__ mio, const float* __restrict__ pw,
                         const float* __restrict__ pb) {
    __shared__ float sw[162];
    __shared__ float sb[18];
    if (threadIdx.x < 162) sw[threadIdx.x] = pw[threadIdx.x];
    if (threadIdx.x < 18)  sb[threadIdx.x] = pb[threadIdx.x];
    __syncthreads();
    int b = blockIdx.y;
    int hw = blockIdx.x * 256 + threadIdx.x;
    int h = hw >> 6, w = hw & 63;
    const float* plane = mio + b * 4096;
    float v[9];
    #pragma unroll
    for (int kh = 0; kh < 3; kh++)
        #pragma unroll
        for (int kw = 0; kw < 3; kw++) {
            int hi = h - 1 + kh, wi = w - 1 + kw;
            v[kh * 3 + kw] = (hi >= 0 && hi < 64 && wi >= 0 && wi < 64) ? plane[hi * 64 + wi] : 0.f;
        }
    #pragma unroll
    for (int n = 0; n < 9; n++) {
        float offx = sb[n], offy = sb[9 + n];
        #pragma unroll
        for (int t = 0; t < 9; t++) {
            offx += v[t] * sw[n * 9 + t];
            offy += v[t] * sw[(9 + n) * 9 + t];
        }
        float px = (float)(h + 1) + (float)(n / 3 - 1) + offx;
        float py = (float)(w + 1) + (float)(n % 3 - 1) + offy;
        float fx = floorf(px), fy = floorf(py);
        int xlt = min(max((int)fx, 0), 65);
        int xrb = min(max((int)fx + 1, 0), 65);
        int ylt = min(max((int)fy, 0), 65);
        int yrb = min(max((int)fy + 1, 0), 65);
        float pcx = fminf(fmaxf(px, 0.f), 65.f);
        float pcy = fminf(fmaxf(py, 0.f), 65.f);
        float glt = (1.f + ((float)xlt - pcx)) * (1.f + ((float)ylt - pcy));
        float grb = (1.f - ((float)xrb - pcx)) * (1.f - ((float)yrb - pcy));
        float glb = (1.f + ((float)xlt - pcx)) * (1.f - ((float)yrb - pcy));
        float grt = (1.f - ((float)xrb - pcx)) * (1.f + ((float)ylt - pcy));
        int base = ((b * 9 + n) * HW4 + hw) * 4;
        *(int4*)(d_idx + base) = make_int4(xlt * 66 + ylt, xrb * 66 + yrb,
                                           xlt * 66 + yrb, xrb * 66 + ylt);
        *(float4*)(d_gw + base) = make_float4(glt, grb, glb, grt);
    }
}

// ---------------- 6. fused gather + transpose + bf16 split: [b][hw][k] ----------------
#define SPITCH 1160          // bf16 pitch per hw row in smem (even)
__global__ __launch_bounds__(256) void k_sample_t() {
    extern __shared__ __nv_bfloat16 smbf[];    // hi [16][1160], lo [16][1160]
    __nv_bfloat16* shi = smbf;
    __nv_bfloat16* slo = smbf + 16 * SPITCH;
    __shared__ int4   sidx[9][16];
    __shared__ float4 sg[9][16];
    int b = blockIdx.y;
    int hw0 = blockIdx.x * 16;
    int tid = threadIdx.x;
    if (tid < 144) {
        int n = tid / 16, hl = tid & 15;
        int base = ((b * 9 + n) * HW4 + hw0 + hl) * 4;
        sidx[n][hl] = *(const int4*)(d_idx + base);
        sg[n][hl]   = *(const float4*)(d_gw + base);
    }
    __syncthreads();
    int hl = tid & 15;
    int cbase = tid >> 4;                      // 0..15
    const float* xpb = d_xpad + (size_t)b * 128 * 4356;
    #pragma unroll
    for (int pass = 0; pass < 8; pass++) {
        int c = pass * 16 + cbase;
        const float* pl = xpb + c * 4356;
        int dbase = hl * SPITCH + c * 9;
        #pragma unroll
        for (int n = 0; n < 9; n++) {
            int4 id = sidx[n][hl];
            float4 g = sg[n][hl];
            float val = g.x * pl[id.x] + g.y * pl[id.y] + g.z * pl[id.z] + g.w * pl[id.w];
            __nv_bfloat16 hi, lo;
            split_bf16(val, hi, lo);
            shi[dbase + n] = hi;
            slo[dbase + n] = lo;
        }
    }
    __syncthreads();
    const uint32_t* shi32 = (const uint32_t*)shi;
    const uint32_t* slo32 = (const uint32_t*)slo;
    uint32_t* ohi = (uint32_t*)d_Bhi + (size_t)(b * HW4 + hw0) * (CN / 2);
    uint32_t* olo = (uint32_t*)d_Blo + (size_t)(b * HW4 + hw0) * (CN / 2);
    #pragma unroll
    for (int j = 0; j < 36; j++) {
        int lin = j * 256 + tid;               // < 9216
        int row = lin / 576, col = lin - row * 576;
        ohi[(size_t)row * 576 + col] = shi32[row * (SPITCH / 2) + col];
        olo[(size_t)row * 576 + col] = slo32[row * (SPITCH / 2) + col];
    }
}

// ---------------- 7. main contraction: bf16x3 mma.sync (ldmatrix) + fused LSTM gates ----------------
// Per b: C[256 o][128 hw tile] = A[256][1152] * B[hw][1152]^T + bias -> gates -> out.
// CTA: 512 threads, 16 warps (4m x 4n), warp tile 64m x 32n. kc=32 double-buffered.
// Grid (32, 4) = 128 CTAs -> single wave.
#define KC 32
#define APITCH 40                          // bf16 per smem row (80 bytes)
#define AHB (256 * APITCH * 2)             // 20480 bytes per A component
#define BHB (128 * APITCH * 2)             // 10240 bytes per B component
#define OFF_AL AHB
#define OFF_BH (2 * AHB)
#define OFF_BL (2 * AHB + BHB)
#define STG (2 * AHB + 2 * BHB)            // 61440
#define GSMEM (256 * 132 * 4)              // 135168 epilogue C staging

__global__ __launch_bounds__(512, 1) void k_gemm_mma(const float* __restrict__ ccur,
                                                     float* __restrict__ out) {
    extern __shared__ char smb[];
    uint32_t s0 = smem_u32(smb);
    int tid = threadIdx.x, wid = tid >> 5, lane = tid & 31;
    int b = blockIdx.y;
    int hw0 = blockIdx.x * 128;

    const __nv_bfloat16* Ahi = d_Ahi + (size_t)b * 256 * CN;
    const __nv_bfloat16* Alo = d_Alo + (size_t)b * 256 * CN;
    const __nv_bfloat16* Bhi = d_Bhi + (size_t)(b * HW4 + hw0) * CN;
    const __nv_bfloat16* Blo = d_Blo + (size_t)(b * HW4 + hw0) * CN;

    auto load_stage = [&](int stage, int k0) {
        uint32_t sa = s0 + stage * STG;
        #pragma unroll
        for (int i = 0; i < 2; i++) {
            int l = tid + i * 512;
            int r = l >> 2, seg = l & 3;
            CP_ASYNC16(sa + r * 80 + seg * 16, Ahi + (size_t)r * CN + k0 + seg * 8);
        }
        #pragma unroll
        for (int i = 0; i < 2; i++) {
            int l = tid + i * 512;
            int r = l >> 2, seg = l & 3;
            CP_ASYNC16(sa + OFF_AL + r * 80 + seg * 16, Alo + (size_t)r * CN + k0 + seg * 8);
        }
        {
            int r = tid >> 2, seg = tid & 3;
            CP_ASYNC16(sa + OFF_BH + r * 80 + seg * 16, Bhi + (size_t)r * CN + k0 + seg * 8);
            CP_ASYNC16(sa + OFF_BL + r * 80 + seg * 16, Blo + (size_t)r * CN + k0 + seg * 8);
        }
    };

    float acc[4][4][4];
    #pragma unroll
    for (int i = 0; i < 4; i++)
        #pragma unroll
        for (int j = 0; j < 4; j++)
            #pragma unroll
            for (int q = 0; q < 4; q++) acc[i][j][q] = 0.f;

    load_stage(0, 0);
    CP_COMMIT();

    int mwarp = (wid & 3) * 64;
    int nwarp = (wid >> 2) * 32;
    int grp = lane >> 2;                   // 0..7
    int tig = lane & 3;                    // 0..3
    // ldmatrix per-lane addressing
    uint32_t aRow = (uint32_t)(mwarp + (lane & 15)) * 80 + (((uint32_t)lane >> 4) << 4);
    int lB = lane & 15;
    uint32_t bRow = (uint32_t)(nwarp + (lB & 7)) * 80 + ((((uint32_t)lB >> 3) & 1) << 4);

    for (int it = 0; it < 36; it++) {
        int cur = it & 1;
        if (it + 1 < 36) {
            load_stage(1 - cur, (it + 1) * KC);
            CP_COMMIT();
            CP_WAIT(1);
        } else {
            CP_WAIT(0);
        }
        __syncthreads();
        uint32_t base = s0 + cur * STG;
        #pragma unroll
        for (int s = 0; s < 2; s++) {
            uint32_t kof = (uint32_t)s * 32;
            uint32_t bh[4][2], bl[4][2];
            #pragma unroll
            for (int nt = 0; nt < 4; nt++) {
                uint32_t ab = base + OFF_BH + bRow + nt * (8 * 80) + kof;
                LDSM_X2(bh[nt][0], bh[nt][1], ab);
                LDSM_X2(bl[nt][0], bl[nt][1], ab + BHB);
            }
            #pragma unroll
            for (int mt = 0; mt < 4; mt++) {
                uint32_t aa = base + aRow + mt * (16 * 80) + kof;
                uint32_t ah[4], al[4];
                LDSM_X4(ah[0], ah[1], ah[2], ah[3], aa);
                LDSM_X4(al[0], al[1], al[2], al[3], aa + AHB);
                #pragma unroll
                for (int nt = 0; nt < 4; nt++) {
                    mma_bf16(acc[mt][nt], ah, bh[nt]);
                    mma_bf16(acc[mt][nt], ah, bl[nt]);
                    mma_bf16(acc[mt][nt], al, bh[nt]);
                }
            }
        }
        __syncthreads();
    }

    // ---- stage C tile (with bias) into smem, then fused LSTM gates ----
    __syncthreads();
    float* Cs = (float*)smb;               // [256][132]
    const float* bmp = d_bm + b * 256;
    #pragma unroll
    for (int mt = 0; mt < 4; mt++) {
        int row = mwarp + mt * 16 + grp;
        float bz0 = bmp[row], bz1 = bmp[row + 8];
        #pragma unroll
        for (int nt = 0; nt < 4; nt++) {
            int col = nwarp + nt * 8 + tig * 2;
            Cs[row * 132 + col]           = acc[mt][nt][0] + bz0;
            Cs[row * 132 + col + 1]       = acc[mt][nt][1] + bz0;
            Cs[(row + 8) * 132 + col]     = acc[mt][nt][2] + bz1;
            Cs[(row + 8) * 132 + col + 1] = acc[mt][nt][3] + bz1;
        }
    }
    __syncthreads();
    #pragma unroll
    for (int q = 0; q < 16; q++) {
        int lin = q * 512 + tid;           // < 8192
        int hid = lin >> 7, hw = lin & 127;
        float ci = Cs[hid * 132 + hw];
        float cf = Cs[(hid + 64) * 132 + hw];
        float co = Cs[(hid + 128) * 132 + hw];
        float cg = Cs[(hid + 192) * 132 + hw];
        float ig = 1.f / (1.f + expf(-ci));
        float fg = 1.f / (1.f + expf(-cf));
        float og = 1.f / (1.f + expf(-co));
        float gg = tanhf(cg);
        int g = (b * 64 + hid) * HW4 + hw0 + hw;
        float cn = fg * ccur[g] + ig * gg;
        float hn = og * tanhf(cn);
        out[g] = hn;
        out[1048576 + g] = cn;
    }
}

// ---------------- launch ----------------
extern "C" void kernel_launch(void* const* d_in, const int* in_sizes, int n_in,
                              void* d_out, int out_size) {
    const float* inp  = (const float*)d_in[0];
    const float* hcur = (const float*)d_in[1];
    const float* ccur = (const float*)d_in[2];
    const float* meta = (const float*)d_in[3];
    const float* mio  = (const float*)d_in[4];
    const float* w1w  = (const float*)d_in[5];
    const float* w1b  = (const float*)d_in[6];
    const float* w2w  = (const float*)d_in[7];
    const float* w2b  = (const float*)d_in[8];
    const float* blw  = (const float*)d_in[9];
    const float* blb  = (const float*)d_in[10];
    const float* pw   = (const float*)d_in[11];
    const float* pb   = (const float*)d_in[12];
    float* out = (float*)d_out;

    cudaFuncSetAttribute(k_sample_t, cudaFuncAttributeMaxDynamicSharedMemorySize,
                         2 * 16 * SPITCH * 2);
    cudaFuncSetAttribute(k_gemm_mma, cudaFuncAttributeMaxDynamicSharedMemorySize, GSMEM);

    k_pad     <<<8712, 256>>>(inp, hcur);
    k_w1      <<<4096, 256>>>(meta, w1w, w1b);
    k_bias    <<<128, 256>>>(meta, blw, blb);
    k_hyper2  <<<dim3(36, 4), 256>>>(w2w, w2b);
    k_offset  <<<dim3(16, 4), 256>>>(mio, pw, pb);
    k_sample_t<<<dim3(256, 4), 256, 2 * 16 * SPITCH * 2>>>();
    k_gemm_mma<<<dim3(32, 4), 512, GSMEM>>>(ccur, out);
}

// round 8
// speedup vs baseline: 2.5061x; 1.0546x over previous
#include <cuda_runtime.h>
#include <cuda_bf16.h>
#include <math.h>
#include <stdint.h>

// B=4, CIN=64, HID=64, H=W=64, K=3, N=9, D=256, INC=128, OUTC=256
// HP=WP=66, HW=4096, CN = INC*9 = 1152
#define HW4 4096
#define CN 1152

// ---------------- scratch ----------------
__device__ __nv_bfloat16  d_t1hi[4 * 128 * 256];            // [row=(b,c)][d] bf16 hi
__device__ __nv_bfloat16  d_t1lo[4 * 128 * 256];            // bf16 lo
__device__ __nv_bfloat16  d_w2hi[2304 * 256];               // [j][d] bf16 hi
__device__ __nv_bfloat16  d_w2lo[2304 * 256];               // bf16 lo
__device__ __nv_bfloat16  d_Ahi[4 * 256 * CN];              // [b][o][k] bf16 hi
__device__ __nv_bfloat16  d_Alo[4 * 256 * CN];              // [b][o][k] bf16 lo
__device__ float          d_bm[4 * 256];                    // [b][o]
__device__ int            d_idx[4 * 9 * HW4 * 4];           // [b][n][hw][4]
__device__ float          d_gw [4 * 9 * HW4 * 4];           // [b][n][hw][4]
__device__ float          d_xpad[4 * 128 * 66 * 66];        // [b][c][66][66]
__device__ __nv_bfloat16  d_Bhi[(size_t)4 * HW4 * CN];      // [b][hw][k] bf16 hi  37.7MB
__device__ __nv_bfloat16  d_Blo[(size_t)4 * HW4 * CN];      // [b][hw][k] bf16 lo  37.7MB

// ---------------- helpers ----------------
__device__ __forceinline__ uint32_t smem_u32(const void* p) {
    uint32_t a;
    asm("{ .reg .u64 t; cvta.to.shared.u64 t, %1; cvt.u32.u64 %0, t; }" : "=r"(a) : "l"(p));
    return a;
}
#define CP_ASYNC16(dst, src) asm volatile("cp.async.cg.shared.global [%0], [%1], 16;" :: "r"(dst), "l"(src))
#define CP_COMMIT()          asm volatile("cp.async.commit_group;" ::: "memory")
#define CP_WAIT(n)           asm volatile("cp.async.wait_group %0;" :: "n"(n) : "memory")
#define LDSM_X4(R0,R1,R2,R3,ADDR) \
    asm volatile("ldmatrix.sync.aligned.m8n8.x4.shared.b16 {%0,%1,%2,%3}, [%4];" \
                 : "=r"(R0),"=r"(R1),"=r"(R2),"=r"(R3) : "r"(ADDR))
#define LDSM_X2(R0,R1,ADDR) \
    asm volatile("ldmatrix.sync.aligned.m8n8.x2.shared.b16 {%0,%1}, [%2];" \
                 : "=r"(R0),"=r"(R1) : "r"(ADDR))

__device__ __forceinline__ void mma_bf16(float* c, const uint32_t* a, const uint32_t* b) {
    asm volatile(
        "mma.sync.aligned.m16n8k16.row.col.f32.bf16.bf16.f32 "
        "{%0,%1,%2,%3}, {%4,%5,%6,%7}, {%8,%9}, {%0,%1,%2,%3};"
        : "+f"(c[0]), "+f"(c[1]), "+f"(c[2]), "+f"(c[3])
        : "r"(a[0]), "r"(a[1]), "r"(a[2]), "r"(a[3]), "r"(b[0]), "r"(b[1]));
}

__device__ __forceinline__ void split_bf16(float v, __nv_bfloat16& hi, __nv_bfloat16& lo) {
    hi = __float2bfloat16(v);
    lo = __float2bfloat16(v - __bfloat162float(hi));
}

// ---------------- 1. concat + ZeroPad2d(1) ----------------
__global__ void k_pad(const float* __restrict__ inp, const float* __restrict__ hcur) {
    int i = blockIdx.x * 256 + threadIdx.x;
    const int total = 4 * 128 * 66 * 66;
    if (i >= total) return;
    int wp = i % 66;
    int t = i / 66;
    int hp = t % 66; t /= 66;
    int c = t % 128; int b = t / 128;
    float v = 0.f;
    if (hp >= 1 && hp <= 64 && wp >= 1 && wp <= 64) {
        int sp = ((b * 64 + (c < 64 ? c : c - 64)) * 64 + (hp - 1)) * 64 + (wp - 1);
        v = (c < 64) ? inp[sp] : hcur[sp];
    }
    d_xpad[i] = v;
}

// ---------------- 2. hyper stage 1 -> bf16 hi/lo tmp1 ----------------
__global__ void k_w1(const float* __restrict__ meta, const float* __restrict__ w1w,
                     const float* __restrict__ w1b) {
    __shared__ float sm[1024];
    for (int i = threadIdx.x; i < 1024; i += 256) sm[i] = meta[i];
    __syncthreads();
    int gw = (blockIdx.x * 256 + threadIdx.x) >> 5;   // 0..32767 = (c,d)
    int lane = threadIdx.x & 31;
    const float* row = w1w + (size_t)gw * 256;
    float a0 = 0.f, a1 = 0.f, a2 = 0.f, a3 = 0.f;
    #pragma unroll
    for (int k = lane; k < 256; k += 32) {
        float wv = row[k];
        a0 += wv * sm[k];       a1 += wv * sm[256 + k];
        a2 += wv * sm[512 + k]; a3 += wv * sm[768 + k];
    }
    #pragma unroll
    for (int s = 16; s > 0; s >>= 1) {
        a0 += __shfl_xor_sync(~0u, a0, s); a1 += __shfl_xor_sync(~0u, a1, s);
        a2 += __shfl_xor_sync(~0u, a2, s); a3 += __shfl_xor_sync(~0u, a3, s);
    }
    if (lane == 0) {
        float bb = w1b[gw];
        float v[4] = {a0 + bb, a1 + bb, a2 + bb, a3 + bb};
        #pragma unroll
        for (int b = 0; b < 4; b++) {
            __nv_bfloat16 hi, lo;
            split_bf16(v[b], hi, lo);
            d_t1hi[b * 32768 + gw] = hi;
            d_t1lo[b * 32768 + gw] = lo;
        }
    }
}

// ---------------- 2b. split w2_w into bf16 hi/lo ----------------
__global__ void k_wsplit(const float* __restrict__ w2w) {
    int i = blockIdx.x * 256 + threadIdx.x;
    if (i >= 2304 * 256) return;
    __nv_bfloat16 hi, lo;
    split_bf16(w2w[i], hi, lo);
    d_w2hi[i] = hi;
    d_w2lo[i] = lo;
}

// ---------------- 3. per-gate bias ----------------
__global__ void k_bias(const float* __restrict__ meta, const float* __restrict__ blw,
                       const float* __restrict__ blb) {
    int gw = (blockIdx.x * 256 + threadIdx.x) >> 5;
    int lane = threadIdx.x & 31;
    int b = gw >> 8, o = gw & 255;
    const float* row = blw + o * 256;
    const float* m = meta + b * 256;
    float a = 0.f;
    for (int k = lane; k < 256; k += 32) a += row[k] * m[k];
    #pragma unroll
    for (int s = 16; s > 0; s >>= 1) a += __shfl_xor_sync(~0u, a, s);
    if (lane == 0) d_bm[gw] = a + blb[o];
}

// ---------------- 4. hyper stage 2: bf16x3 mma GEMM 512x2304x256 -> A hi/lo ----------------
// C[row=(b,c)][j=(o,n)] = tmp1[row][d] . w2w[j][d] + w2b[j]; tile 128x128, 8 warps.
#define H2P 80                             // smem row pitch bytes (40 bf16)
#define H2A (128 * H2P)                    // 10240 per component
#define H2STG (4 * H2A)                    // 40960
__global__ __launch_bounds__(256, 1) void k_hyper2(const float* __restrict__ w2b) {
    extern __shared__ char smb[];
    uint32_t s0 = smem_u32(smb);
    int tid = threadIdx.x, wid = tid >> 5, lane = tid & 31;
    int row0 = blockIdx.y * 128;           // 512 rows
    int col0 = blockIdx.x * 128;           // 2304 cols

    const __nv_bfloat16* Ahi = d_t1hi;
    const __nv_bfloat16* Alo = d_t1lo;

    auto load_stage = [&](int stage, int k0) {
        uint32_t sa = s0 + stage * H2STG;
        #pragma unroll
        for (int i = 0; i < 2; i++) {
            int l = tid + i * 256;
            int r = l >> 2, seg = l & 3;
            CP_ASYNC16(sa + r * H2P + seg * 16,
                       Ahi + (size_t)(row0 + r) * 256 + k0 + seg * 8);
        }
        #pragma unroll
        for (int i = 0; i < 2; i++) {
            int l = tid + i * 256;
            int r = l >> 2, seg = l & 3;
            CP_ASYNC16(sa + H2A + r * H2P + seg * 16,
                       Alo + (size_t)(row0 + r) * 256 + k0 + seg * 8);
        }
        #pragma unroll
        for (int i = 0; i < 2; i++) {
            int l = tid + i * 256;
            int r = l >> 2, seg = l & 3;
            CP_ASYNC16(sa + 2 * H2A + r * H2P + seg * 16,
                       d_w2hi + (size_t)(col0 + r) * 256 + k0 + seg * 8);
        }
        #pragma unroll
        for (int i = 0; i < 2; i++) {
            int l = tid + i * 256;
            int r = l >> 2, seg = l & 3;
            CP_ASYNC16(sa + 3 * H2A + r * H2P + seg * 16,
                       d_w2lo + (size_t)(col0 + r) * 256 + k0 + seg * 8);
        }
    };

    float acc[4][4][4];
    #pragma unroll
    for (int i = 0; i < 4; i++)
        #pragma unroll
        for (int j = 0; j < 4; j++)
            #pragma unroll
            for (int q = 0; q < 4; q++) acc[i][j][q] = 0.f;

    load_stage(0, 0);
    CP_COMMIT();

    int mwarp = (wid & 1) * 64;
    int nwarp = (wid >> 1) * 32;
    int grp = lane >> 2, tig = lane & 3;
    uint32_t aRow = (uint32_t)(mwarp + (lane & 15)) * H2P + (((uint32_t)lane >> 4) << 4);
    int lB = lane & 15;
    uint32_t bRow = (uint32_t)(nwarp + (lB & 7)) * H2P + ((((uint32_t)lB >> 3) & 1) << 4);

    for (int it = 0; it < 8; it++) {
        int cur = it & 1;
        if (it + 1 < 8) {
            load_stage(1 - cur, (it + 1) * 32);
            CP_COMMIT();
            CP_WAIT(1);
        } else {
            CP_WAIT(0);
        }
        __syncthreads();
        uint32_t base = s0 + cur * H2STG;
        #pragma unroll
        for (int s = 0; s < 2; s++) {
            uint32_t kof = (uint32_t)s * 32;
            uint32_t bh[4][2], bl[4][2];
            #pragma unroll
            for (int nt = 0; nt < 4; nt++) {
                uint32_t ab = base + 2 * H2A + bRow + nt * (8 * H2P) + kof;
                LDSM_X2(bh[nt][0], bh[nt][1], ab);
                LDSM_X2(bl[nt][0], bl[nt][1], ab + H2A);
            }
            #pragma unroll
            for (int mt = 0; mt < 4; mt++) {
                uint32_t aa = base + aRow + mt * (16 * H2P) + kof;
                uint32_t ah[4], al[4];
                LDSM_X4(ah[0], ah[1], ah[2], ah[3], aa);
                LDSM_X4(al[0], al[1], al[2], al[3], aa + H2A);
                #pragma unroll
                for (int nt = 0; nt < 4; nt++) {
                    mma_bf16(acc[mt][nt], ah, bh[nt]);
                    mma_bf16(acc[mt][nt], ah, bl[nt]);
                    mma_bf16(acc[mt][nt], al, bh[nt]);
                }
            }
        }
        __syncthreads();
    }

    // epilogue: add w2b, split, scatter to d_Ahi/d_Alo [(b,o)][c*9+n]
    #pragma unroll
    for (int mt = 0; mt < 4; mt++) {
        #pragma unroll
        for (int nt = 0; nt < 4; nt++) {
            #pragma unroll
            for (int q = 0; q < 4; q++) {
                int rloc = mwarp + mt * 16 + grp + ((q >> 1) ? 8 : 0);
                int cloc = nwarp + nt * 8 + tig * 2 + (q & 1);
                int gr = row0 + rloc;
                int jj = col0 + cloc;
                int b = gr >> 7, c = gr & 127;
                int o = jj / 9, n = jj - o * 9;
                size_t dst = ((size_t)(b * 256 + o)) * CN + c * 9 + n;
                __nv_bfloat16 hi, lo;
                split_bf16(acc[mt][nt][q] + w2b[jj], hi, lo);
                d_Ahi[dst] = hi;
                d_Alo[dst] = lo;
            }
        }
    }
}

// ---------------- 5. offset conv + positions/weights ----------------
__global__ void k_offset(const float* __restrict__ mio, const float* __restrict__ pw,
                         const float* __restrict__ pb) {
    __shared__ float sw[162];
    __shared__ float sb[18];
    if (threadIdx.x < 162) sw[threadIdx.x] = pw[threadIdx.x];
    if (threadIdx.x < 18)  sb[threadIdx.x] = pb[threadIdx.x];
    __syncthreads();
    int b = blockIdx.y;
    int hw = blockIdx.x * 256 + threadIdx.x;
    int h = hw >> 6, w = hw & 63;
    const float* plane = mio + b * 4096;
    float v[9];
    #pragma unroll
    for (int kh = 0; kh < 3; kh++)
        #pragma unroll
        for (int kw = 0; kw < 3; kw++) {
            int hi = h - 1 + kh, wi = w - 1 + kw;
            v[kh * 3 + kw] = (hi >= 0 && hi < 64 && wi >= 0 && wi < 64) ? plane[hi * 64 + wi] : 0.f;
        }
    #pragma unroll
    for (int n = 0; n < 9; n++) {
        float offx = sb[n], offy = sb[9 + n];
        #pragma unroll
        for (int t = 0; t < 9; t++) {
            offx += v[t] * sw[n * 9 + t];
            offy += v[t] * sw[(9 + n) * 9 + t];
        }
        float px = (float)(h + 1) + (float)(n / 3 - 1) + offx;
        float py = (float)(w + 1) + (float)(n % 3 - 1) + offy;
        float fx = floorf(px), fy = floorf(py);
        int xlt = min(max((int)fx, 0), 65);
        int xrb = min(max((int)fx + 1, 0), 65);
        int ylt = min(max((int)fy, 0), 65);
        int yrb = min(max((int)fy + 1, 0), 65);
        float pcx = fminf(fmaxf(px, 0.f), 65.f);
        float pcy = fminf(fmaxf(py, 0.f), 65.f);
        float glt = (1.f + ((float)xlt - pcx)) * (1.f + ((float)ylt - pcy));
        float grb = (1.f - ((float)xrb - pcx)) * (1.f - ((float)yrb - pcy));
        float glb = (1.f + ((float)xlt - pcx)) * (1.f - ((float)yrb - pcy));
        float grt = (1.f - ((float)xrb - pcx)) * (1.f + ((float)ylt - pcy));
        int base = ((b * 9 + n) * HW4 + hw) * 4;
        *(int4*)(d_idx + base) = make_int4(xlt * 66 + ylt, xrb * 66 + yrb,
                                           xlt * 66 + yrb, xrb * 66 + ylt);
        *(float4*)(d_gw + base) = make_float4(glt, grb, glb, grt);
    }
}

// ---------------- 6. fused gather + transpose + bf16 split: [b][hw][k] ----------------
#define SPITCH 1160          // bf16 pitch per hw row in smem (even)
__global__ __launch_bounds__(256) void k_sample_t() {
    extern __shared__ __nv_bfloat16 smbf[];    // hi [16][1160], lo [16][1160]
    __nv_bfloat16* shi = smbf;
    __nv_bfloat16* slo = smbf + 16 * SPITCH;
    __shared__ int4   sidx[9][16];
    __shared__ float4 sg[9][16];
    int b = blockIdx.y;
    int hw0 = blockIdx.x * 16;
    int tid = threadIdx.x;
    if (tid < 144) {
        int n = tid / 16, hl = tid & 15;
        int base = ((b * 9 + n) * HW4 + hw0 + hl) * 4;
        sidx[n][hl] = *(const int4*)(d_idx + base);
        sg[n][hl]   = *(const float4*)(d_gw + base);
    }
    __syncthreads();
    int hl = tid & 15;
    int cbase = tid >> 4;                      // 0..15
    const float* xpb = d_xpad + (size_t)b * 128 * 4356;
    #pragma unroll
    for (int pass = 0; pass < 8; pass++) {
        int c = pass * 16 + cbase;
        const float* pl = xpb + c * 4356;
        int dbase = hl * SPITCH + c * 9;
        #pragma unroll
        for (int n = 0; n < 9; n++) {
            int4 id = sidx[n][hl];
            float4 g = sg[n][hl];
            float val = g.x * pl[id.x] + g.y * pl[id.y] + g.z * pl[id.z] + g.w * pl[id.w];
            __nv_bfloat16 hi, lo;
            split_bf16(val, hi, lo);
            shi[dbase + n] = hi;
            slo[dbase + n] = lo;
        }
    }
    __syncthreads();
    const uint32_t* shi32 = (const uint32_t*)shi;
    const uint32_t* slo32 = (const uint32_t*)slo;
    uint32_t* ohi = (uint32_t*)d_Bhi + (size_t)(b * HW4 + hw0) * (CN / 2);
    uint32_t* olo = (uint32_t*)d_Blo + (size_t)(b * HW4 + hw0) * (CN / 2);
    #pragma unroll
    for (int j = 0; j < 36; j++) {
        int lin = j * 256 + tid;               // < 9216
        int row = lin / 576, col = lin - row * 576;
        ohi[(size_t)row * 576 + col] = shi32[row * (SPITCH / 2) + col];
        olo[(size_t)row * 576 + col] = slo32[row * (SPITCH / 2) + col];
    }
}

// ---------------- 7. main contraction: bf16x3 mma.sync (ldmatrix) + fused LSTM gates ----------------
#define KC 32
#define APITCH 40
#define AHB (256 * APITCH * 2)             // 20480
#define BHB (128 * APITCH * 2)             // 10240
#define OFF_AL AHB
#define OFF_BH (2 * AHB)
#define OFF_BL (2 * AHB + BHB)
#define STG (2 * AHB + 2 * BHB)            // 61440
#define GSMEM (256 * 132 * 4)              // 135168

__global__ __launch_bounds__(512, 1) void k_gemm_mma(const float* __restrict__ ccur,
                                                     float* __restrict__ out) {
    extern __shared__ char smb[];
    uint32_t s0 = smem_u32(smb);
    int tid = threadIdx.x, wid = tid >> 5, lane = tid & 31;
    int b = blockIdx.y;
    int hw0 = blockIdx.x * 128;

    const __nv_bfloat16* Ahi = d_Ahi + (size_t)b * 256 * CN;
    const __nv_bfloat16* Alo = d_Alo + (size_t)b * 256 * CN;
    const __nv_bfloat16* Bhi = d_Bhi + (size_t)(b * HW4 + hw0) * CN;
    const __nv_bfloat16* Blo = d_Blo + (size_t)(b * HW4 + hw0) * CN;

    auto load_stage = [&](int stage, int k0) {
        uint32_t sa = s0 + stage * STG;
        #pragma unroll
        for (int i = 0; i < 2; i++) {
            int l = tid + i * 512;
            int r = l >> 2, seg = l & 3;
            CP_ASYNC16(sa + r * 80 + seg * 16, Ahi + (size_t)r * CN + k0 + seg * 8);
        }
        #pragma unroll
        for (int i = 0; i < 2; i++) {
            int l = tid + i * 512;
            int r = l >> 2, seg = l & 3;
            CP_ASYNC16(sa + OFF_AL + r * 80 + seg * 16, Alo + (size_t)r * CN + k0 + seg * 8);
        }
        {
            int r = tid >> 2, seg = tid & 3;
            CP_ASYNC16(sa + OFF_BH + r * 80 + seg * 16, Bhi + (size_t)r * CN + k0 + seg * 8);
            CP_ASYNC16(sa + OFF_BL + r * 80 + seg * 16, Blo + (size_t)r * CN + k0 + seg * 8);
        }
    };

    float acc[4][4][4];
    #pragma unroll
    for (int i = 0; i < 4; i++)
        #pragma unroll
        for (int j = 0; j < 4; j++)
            #pragma unroll
            for (int q = 0; q < 4; q++) acc[i][j][q] = 0.f;

    load_stage(0, 0);
    CP_COMMIT();

    int mwarp = (wid & 3) * 64;
    int nwarp = (wid >> 2) * 32;
    int grp = lane >> 2, tig = lane & 3;
    uint32_t aRow = (uint32_t)(mwarp + (lane & 15)) * 80 + (((uint32_t)lane >> 4) << 4);
    int lB = lane & 15;
    uint32_t bRow = (uint32_t)(nwarp + (lB & 7)) * 80 + ((((uint32_t)lB >> 3) & 1) << 4);

    for (int it = 0; it < 36; it++) {
        int cur = it & 1;
        if (it + 1 < 36) {
            load_stage(1 - cur, (it + 1) * KC);
            CP_COMMIT();
            CP_WAIT(1);
        } else {
            CP_WAIT(0);
        }
        __syncthreads();
        uint32_t base = s0 + cur * STG;
        #pragma unroll
        for (int s = 0; s < 2; s++) {
            uint32_t kof = (uint32_t)s * 32;
            uint32_t bh[4][2], bl[4][2];
            #pragma unroll
            for (int nt = 0; nt < 4; nt++) {
                uint32_t ab = base + OFF_BH + bRow + nt * (8 * 80) + kof;
                LDSM_X2(bh[nt][0], bh[nt][1], ab);
                LDSM_X2(bl[nt][0], bl[nt][1], ab + BHB);
            }
            #pragma unroll
            for (int mt = 0; mt < 4; mt++) {
                uint32_t aa = base + aRow + mt * (16 * 80) + kof;
                uint32_t ah[4], al[4];
                LDSM_X4(ah[0], ah[1], ah[2], ah[3], aa);
                LDSM_X4(al[0], al[1], al[2], al[3], aa + AHB);
                #pragma unroll
                for (int nt = 0; nt < 4; nt++) {
                    mma_bf16(acc[mt][nt], ah, bh[nt]);
                    mma_bf16(acc[mt][nt], ah, bl[nt]);
                    mma_bf16(acc[mt][nt], al, bh[nt]);
                }
            }
        }
        __syncthreads();
    }

    // ---- stage C tile (with bias) into smem, then fused LSTM gates ----
    __syncthreads();
    float* Cs = (float*)smb;               // [256][132]
    const float* bmp = d_bm + b * 256;
    #pragma unroll
    for (int mt = 0; mt < 4; mt++) {
        int row = mwarp + mt * 16 + grp;
        float bz0 = bmp[row], bz1 = bmp[row + 8];
        #pragma unroll
        for (int nt = 0; nt < 4; nt++) {
            int col = nwarp + nt * 8 + tig * 2;
            Cs[row * 132 + col]           = acc[mt][nt][0] + bz0;
            Cs[row * 132 + col + 1]       = acc[mt][nt][1] + bz0;
            Cs[(row + 8) * 132 + col]     = acc[mt][nt][2] + bz1;
            Cs[(row + 8) * 132 + col + 1] = acc[mt][nt][3] + bz1;
        }
    }
    __syncthreads();
    #pragma unroll
    for (int q = 0; q < 16; q++) {
        int lin = q * 512 + tid;           // < 8192
        int hid = lin >> 7, hw = lin & 127;
        float ci = Cs[hid * 132 + hw];
        float cf = Cs[(hid + 64) * 132 + hw];
        float co = Cs[(hid + 128) * 132 + hw];
        float cg = Cs[(hid + 192) * 132 + hw];
        float ig = 1.f / (1.f + expf(-ci));
        float fg = 1.f / (1.f + expf(-cf));
        float og = 1.f / (1.f + expf(-co));
        float gg = tanhf(cg);
        int g = (b * 64 + hid) * HW4 + hw0 + hw;
        float cn = fg * ccur[g] + ig * gg;
        float hn = og * tanhf(cn);
        out[g] = hn;
        out[1048576 + g] = cn;
    }
}

// ---------------- launch ----------------
extern "C" void kernel_launch(void* const* d_in, const int* in_sizes, int n_in,
                              void* d_out, int out_size) {
    const float* inp  = (const float*)d_in[0];
    const float* hcur = (const float*)d_in[1];
    const float* ccur = (const float*)d_in[2];
    const float* meta = (const float*)d_in[3];
    const float* mio  = (const float*)d_in[4];
    const float* w1w  = (const float*)d_in[5];
    const float* w1b  = (const float*)d_in[6];
    const float* w2w  = (const float*)d_in[7];
    const float* w2b  = (const float*)d_in[8];
    const float* blw  = (const float*)d_in[9];
    const float* blb  = (const float*)d_in[10];
    const float* pw   = (const float*)d_in[11];
    const float* pb   = (const float*)d_in[12];
    float* out = (float*)d_out;

    cudaFuncSetAttribute(k_hyper2, cudaFuncAttributeMaxDynamicSharedMemorySize, 2 * H2STG);
    cudaFuncSetAttribute(k_sample_t, cudaFuncAttributeMaxDynamicSharedMemorySize,
                         2 * 16 * SPITCH * 2);
    cudaFuncSetAttribute(k_gemm_mma, cudaFuncAttributeMaxDynamicSharedMemorySize, GSMEM);

    k_pad     <<<8712, 256>>>(inp, hcur);
    k_w1      <<<4096, 256>>>(meta, w1w, w1b);
    k_wsplit  <<<2304, 256>>>(w2w);
    k_bias    <<<128, 256>>>(meta, blw, blb);
    k_hyper2  <<<dim3(18, 4), 256, 2 * H2STG>>>(w2b);
    k_offset  <<<dim3(16, 4), 256>>>(mio, pw, pb);
    k_sample_t<<<dim3(256, 4), 256, 2 * 16 * SPITCH * 2>>>();
    k_gemm_mma<<<dim3(32, 4), 512, GSMEM>>>(ccur, out);
}

// round 9
// speedup vs baseline: 2.5263x; 1.0081x over previous
#include <cuda_runtime.h>
#include <cuda_bf16.h>
#include <math.h>
#include <stdint.h>

// B=4, CIN=64, HID=64, H=W=64, K=3, N=9, D=256, INC=128, OUTC=256
// HW=4096, CN = INC*9 = 1152
#define HW4 4096
#define CN 1152

// ---------------- scratch ----------------
__device__ __nv_bfloat16  d_t1hi[4 * 128 * 256];            // [row=(b,c)][d] bf16 hi
__device__ __nv_bfloat16  d_t1lo[4 * 128 * 256];            // bf16 lo
__device__ __nv_bfloat16  d_w2hi[2304 * 256];               // [j][d] bf16 hi
__device__ __nv_bfloat16  d_w2lo[2304 * 256];               // bf16 lo
__device__ __nv_bfloat16  d_Ahi[4 * 256 * CN];              // [b][o][k] bf16 hi
__device__ __nv_bfloat16  d_Alo[4 * 256 * CN];              // bf16 lo
__device__ float          d_bm[4 * 256];                    // [b][o]
__device__ int            d_idx[4 * 9 * HW4 * 4];           // [b][n][hw][4] masked idx (unpadded)
__device__ float          d_gw [4 * 9 * HW4 * 4];           // [b][n][hw][4] masked weights
__device__ __nv_bfloat16  d_Bhi[(size_t)4 * HW4 * CN];      // [b][hw][k] bf16 hi
__device__ __nv_bfloat16  d_Blo[(size_t)4 * HW4 * CN];      // bf16 lo

// ---------------- helpers ----------------
__device__ __forceinline__ uint32_t smem_u32(const void* p) {
    uint32_t a;
    asm("{ .reg .u64 t; cvta.to.shared.u64 t, %1; cvt.u32.u64 %0, t; }" : "=r"(a) : "l"(p));
    return a;
}
#define CP_ASYNC16(dst, src) asm volatile("cp.async.cg.shared.global [%0], [%1], 16;" :: "r"(dst), "l"(src))
#define CP_COMMIT()          asm volatile("cp.async.commit_group;" ::: "memory")
#define CP_WAIT(n)           asm volatile("cp.async.wait_group %0;" :: "n"(n) : "memory")
#define LDSM_X4(R0,R1,R2,R3,ADDR) \
    asm volatile("ldmatrix.sync.aligned.m8n8.x4.shared.b16 {%0,%1,%2,%3}, [%4];" \
                 : "=r"(R0),"=r"(R1),"=r"(R2),"=r"(R3) : "r"(ADDR))
#define LDSM_X2(R0,R1,ADDR) \
    asm volatile("ldmatrix.sync.aligned.m8n8.x2.shared.b16 {%0,%1}, [%2];" \
                 : "=r"(R0),"=r"(R1) : "r"(ADDR))

__device__ __forceinline__ void mma_bf16(float* c, const uint32_t* a, const uint32_t* b) {
    asm volatile(
        "mma.sync.aligned.m16n8k16.row.col.f32.bf16.bf16.f32 "
        "{%0,%1,%2,%3}, {%4,%5,%6,%7}, {%8,%9}, {%0,%1,%2,%3};"
        : "+f"(c[0]), "+f"(c[1]), "+f"(c[2]), "+f"(c[3])
        : "r"(a[0]), "r"(a[1]), "r"(a[2]), "r"(a[3]), "r"(b[0]), "r"(b[1]));
}

__device__ __forceinline__ void split_bf16(float v, __nv_bfloat16& hi, __nv_bfloat16& lo) {
    hi = __float2bfloat16(v);
    lo = __float2bfloat16(v - __bfloat162float(hi));
}

// ---------------- 1. hyper stage 1 -> bf16 hi/lo tmp1 ----------------
__global__ void k_w1(const float* __restrict__ meta, const float* __restrict__ w1w,
                     const float* __restrict__ w1b) {
    __shared__ float sm[1024];
    for (int i = threadIdx.x; i < 1024; i += 256) sm[i] = meta[i];
    __syncthreads();
    int gw = (blockIdx.x * 256 + threadIdx.x) >> 5;   // 0..32767 = (c,d)
    int lane = threadIdx.x & 31;
    const float* row = w1w + (size_t)gw * 256;
    float a0 = 0.f, a1 = 0.f, a2 = 0.f, a3 = 0.f;
    #pragma unroll
    for (int k = lane; k < 256; k += 32) {
        float wv = row[k];
        a0 += wv * sm[k];       a1 += wv * sm[256 + k];
        a2 += wv * sm[512 + k]; a3 += wv * sm[768 + k];
    }
    #pragma unroll
    for (int s = 16; s > 0; s >>= 1) {
        a0 += __shfl_xor_sync(~0u, a0, s); a1 += __shfl_xor_sync(~0u, a1, s);
        a2 += __shfl_xor_sync(~0u, a2, s); a3 += __shfl_xor_sync(~0u, a3, s);
    }
    if (lane == 0) {
        float bb = w1b[gw];
        float v[4] = {a0 + bb, a1 + bb, a2 + bb, a3 + bb};
        #pragma unroll
        for (int b = 0; b < 4; b++) {
            __nv_bfloat16 hi, lo;
            split_bf16(v[b], hi, lo);
            d_t1hi[b * 32768 + gw] = hi;
            d_t1lo[b * 32768 + gw] = lo;
        }
    }
}

// ---------------- 2. merged: split w2_w (blocks 0..2303) + gate bias (blocks 2304..2431) ----------------
__global__ void k_wb(const float* __restrict__ w2w, const float* __restrict__ meta,
                     const float* __restrict__ blw, const float* __restrict__ blb) {
    int bid = blockIdx.x;
    if (bid < 2304) {
        int i = bid * 256 + threadIdx.x;
        __nv_bfloat16 hi, lo;
        split_bf16(w2w[i], hi, lo);
        d_w2hi[i] = hi;
        d_w2lo[i] = lo;
    } else {
        int gw = ((bid - 2304) * 256 + threadIdx.x) >> 5;  // 0..1023
        int lane = threadIdx.x & 31;
        int b = gw >> 8, o = gw & 255;
        const float* row = blw + o * 256;
        const float* m = meta + b * 256;
        float a = 0.f;
        #pragma unroll
        for (int k = lane; k < 256; k += 32) a += row[k] * m[k];
        #pragma unroll
        for (int s = 16; s > 0; s >>= 1) a += __shfl_xor_sync(~0u, a, s);
        if (lane == 0) d_bm[gw] = a + blb[o];
    }
}

// ---------------- 3. offset conv + masked sampling indices/weights (unpadded space) ----------------
__global__ void k_offset(const float* __restrict__ mio, const float* __restrict__ pw,
                         const float* __restrict__ pb) {
    __shared__ float sw[162];
    __shared__ float sb[18];
    if (threadIdx.x < 162) sw[threadIdx.x] = pw[threadIdx.x];
    if (threadIdx.x < 18)  sb[threadIdx.x] = pb[threadIdx.x];
    __syncthreads();
    int b = blockIdx.y;
    int hw = blockIdx.x * 256 + threadIdx.x;
    int h = hw >> 6, w = hw & 63;
    const float* plane = mio + b * 4096;
    float v[9];
    #pragma unroll
    for (int kh = 0; kh < 3; kh++)
        #pragma unroll
        for (int kw = 0; kw < 3; kw++) {
            int hi = h - 1 + kh, wi = w - 1 + kw;
            v[kh * 3 + kw] = (hi >= 0 && hi < 64 && wi >= 0 && wi < 64) ? plane[hi * 64 + wi] : 0.f;
        }
    #pragma unroll
    for (int n = 0; n < 9; n++) {
        float offx = sb[n], offy = sb[9 + n];
        #pragma unroll
        for (int t = 0; t < 9; t++) {
            offx += v[t] * sw[n * 9 + t];
            offy += v[t] * sw[(9 + n) * 9 + t];
        }
        float px = (float)(h + 1) + (float)(n / 3 - 1) + offx;
        float py = (float)(w + 1) + (float)(n % 3 - 1) + offy;
        float fx = floorf(px), fy = floorf(py);
        int xlt = min(max((int)fx, 0), 65);
        int xrb = min(max((int)fx + 1, 0), 65);
        int ylt = min(max((int)fy, 0), 65);
        int yrb = min(max((int)fy + 1, 0), 65);
        float pcx = fminf(fmaxf(px, 0.f), 65.f);
        float pcy = fminf(fmaxf(py, 0.f), 65.f);
        float glt = (1.f + ((float)xlt - pcx)) * (1.f + ((float)ylt - pcy));
        float grb = (1.f - ((float)xrb - pcx)) * (1.f - ((float)yrb - pcy));
        float glb = (1.f + ((float)xlt - pcx)) * (1.f - ((float)yrb - pcy));
        float grt = (1.f - ((float)xrb - pcx)) * (1.f + ((float)ylt - pcy));
        // mask to unpadded 64x64: border corners read padded zeros -> weight 0
        int4 id;
        float4 g;
        #define MASK(X, Y, G, IDX, GO) { \
            bool vv = ((X) >= 1) && ((X) <= 64) && ((Y) >= 1) && ((Y) <= 64); \
            IDX = vv ? (((X) - 1) * 64 + ((Y) - 1)) : 0; \
            GO = vv ? (G) : 0.f; }
        MASK(xlt, ylt, glt, id.x, g.x);
        MASK(xrb, yrb, grb, id.y, g.y);
        MASK(xlt, yrb, glb, id.z, g.z);
        MASK(xrb, ylt, grt, id.w, g.w);
        #undef MASK
        int base = ((b * 9 + n) * HW4 + hw) * 4;
        *(int4*)(d_idx + base) = id;
        *(float4*)(d_gw + base) = g;
    }
}

// ---------------- 4. hyper stage 2: bf16x3 mma GEMM 512x2304x256 -> A hi/lo ----------------
#define H2P 80
#define H2A (128 * H2P)
#define H2STG (4 * H2A)
__global__ __launch_bounds__(256, 1) void k_hyper2(const float* __restrict__ w2b) {
    extern __shared__ char smb[];
    uint32_t s0 = smem_u32(smb);
    int tid = threadIdx.x, wid = tid >> 5, lane = tid & 31;
    int row0 = blockIdx.y * 128;
    int col0 = blockIdx.x * 128;

    auto load_stage = [&](int stage, int k0) {
        uint32_t sa = s0 + stage * H2STG;
        #pragma unroll
        for (int i = 0; i < 2; i++) {
            int l = tid + i * 256;
            int r = l >> 2, seg = l & 3;
            CP_ASYNC16(sa + r * H2P + seg * 16,
                       d_t1hi + (size_t)(row0 + r) * 256 + k0 + seg * 8);
        }
        #pragma unroll
        for (int i = 0; i < 2; i++) {
            int l = tid + i * 256;
            int r = l >> 2, seg = l & 3;
            CP_ASYNC16(sa + H2A + r * H2P + seg * 16,
                       d_t1lo + (size_t)(row0 + r) * 256 + k0 + seg * 8);
        }
        #pragma unroll
        for (int i = 0; i < 2; i++) {
            int l = tid + i * 256;
            int r = l >> 2, seg = l & 3;
            CP_ASYNC16(sa + 2 * H2A + r * H2P + seg * 16,
                       d_w2hi + (size_t)(col0 + r) * 256 + k0 + seg * 8);
        }
        #pragma unroll
        for (int i = 0; i < 2; i++) {
            int l = tid + i * 256;
            int r = l >> 2, seg = l & 3;
            CP_ASYNC16(sa + 3 * H2A + r * H2P + seg * 16,
                       d_w2lo + (size_t)(col0 + r) * 256 + k0 + seg * 8);
        }
    };

    float acc[4][4][4];
    #pragma unroll
    for (int i = 0; i < 4; i++)
        #pragma unroll
        for (int j = 0; j < 4; j++)
            #pragma unroll
            for (int q = 0; q < 4; q++) acc[i][j][q] = 0.f;

    load_stage(0, 0);
    CP_COMMIT();

    int mwarp = (wid & 1) * 64;
    int nwarp = (wid >> 1) * 32;
    int grp = lane >> 2, tig = lane & 3;
    uint32_t aRow = (uint32_t)(mwarp + (lane & 15)) * H2P + (((uint32_t)lane >> 4) << 4);
    int lB = lane & 15;
    uint32_t bRow = (uint32_t)(nwarp + (lB & 7)) * H2P + ((((uint32_t)lB >> 3) & 1) << 4);

    for (int it = 0; it < 8; it++) {
        int cur = it & 1;
        if (it + 1 < 8) {
            load_stage(1 - cur, (it + 1) * 32);
            CP_COMMIT();
            CP_WAIT(1);
        } else {
            CP_WAIT(0);
        }
        __syncthreads();
        uint32_t base = s0 + cur * H2STG;
        #pragma unroll
        for (int s = 0; s < 2; s++) {
            uint32_t kof = (uint32_t)s * 32;
            uint32_t bh[4][2], bl[4][2];
            #pragma unroll
            for (int nt = 0; nt < 4; nt++) {
                uint32_t ab = base + 2 * H2A + bRow + nt * (8 * H2P) + kof;
                LDSM_X2(bh[nt][0], bh[nt][1], ab);
                LDSM_X2(bl[nt][0], bl[nt][1], ab + H2A);
            }
            #pragma unroll
            for (int mt = 0; mt < 4; mt++) {
                uint32_t aa = base + aRow + mt * (16 * H2P) + kof;
                uint32_t ah[4], al[4];
                LDSM_X4(ah[0], ah[1], ah[2], ah[3], aa);
                LDSM_X4(al[0], al[1], al[2], al[3], aa + H2A);
                #pragma unroll
                for (int nt = 0; nt < 4; nt++) {
                    mma_bf16(acc[mt][nt], ah, bh[nt]);
                    mma_bf16(acc[mt][nt], ah, bl[nt]);
                    mma_bf16(acc[mt][nt], al, bh[nt]);
                }
            }
        }
        __syncthreads();
    }

    #pragma unroll
    for (int mt = 0; mt < 4; mt++) {
        #pragma unroll
        for (int nt = 0; nt < 4; nt++) {
            #pragma unroll
            for (int q = 0; q < 4; q++) {
                int rloc = mwarp + mt * 16 + grp + ((q >> 1) ? 8 : 0);
                int cloc = nwarp + nt * 8 + tig * 2 + (q & 1);
                int gr = row0 + rloc;
                int jj = col0 + cloc;
                int b = gr >> 7, c = gr & 127;
                int o = jj / 9, n = jj - o * 9;
                size_t dst = ((size_t)(b * 256 + o)) * CN + c * 9 + n;
                __nv_bfloat16 hi, lo;
                split_bf16(acc[mt][nt][q] + w2b[jj], hi, lo);
                d_Ahi[dst] = hi;
                d_Alo[dst] = lo;
            }
        }
    }
}

// ---------------- 5. fused gather (direct from inp/hcur) + transpose + bf16 split ----------------
#define SPITCH 1160
__global__ __launch_bounds__(256) void k_sample_t(const float* __restrict__ inp,
                                                  const float* __restrict__ hcur) {
    extern __shared__ __nv_bfloat16 smbf[];
    __nv_bfloat16* shi = smbf;
    __nv_bfloat16* slo = smbf + 16 * SPITCH;
    __shared__ int4   sidx[9][16];
    __shared__ float4 sg[9][16];
    int b = blockIdx.y;
    int hw0 = blockIdx.x * 16;
    int tid = threadIdx.x;
    if (tid < 144) {
        int n = tid / 16, hl = tid & 15;
        int base = ((b * 9 + n) * HW4 + hw0 + hl) * 4;
        sidx[n][hl] = *(const int4*)(d_idx + base);
        sg[n][hl]   = *(const float4*)(d_gw + base);
    }
    __syncthreads();
    int hl = tid & 15;
    int cbase = tid >> 4;
    const float* ibase = inp + (size_t)b * 64 * 4096;
    const float* hbase = hcur + (size_t)b * 64 * 4096;
    #pragma unroll
    for (int pass = 0; pass < 8; pass++) {
        int c = pass * 16 + cbase;
        const float* pl = (c < 64) ? (ibase + c * 4096) : (hbase + (c - 64) * 4096);
        int dbase = hl * SPITCH + c * 9;
        #pragma unroll
        for (int n = 0; n < 9; n++) {
            int4 id = sidx[n][hl];
            float4 g = sg[n][hl];
            float val = g.x * pl[id.x] + g.y * pl[id.y] + g.z * pl[id.z] + g.w * pl[id.w];
            __nv_bfloat16 hi, lo;
            split_bf16(val, hi, lo);
            shi[dbase + n] = hi;
            slo[dbase + n] = lo;
        }
    }
    __syncthreads();
    const uint32_t* shi32 = (const uint32_t*)shi;
    const uint32_t* slo32 = (const uint32_t*)slo;
    uint32_t* ohi = (uint32_t*)d_Bhi + (size_t)(b * HW4 + hw0) * (CN / 2);
    uint32_t* olo = (uint32_t*)d_Blo + (size_t)(b * HW4 + hw0) * (CN / 2);
    #pragma unroll
    for (int j = 0; j < 36; j++) {
        int lin = j * 256 + tid;
        int row = lin / 576, col = lin - row * 576;
        ohi[(size_t)row * 576 + col] = shi32[row * (SPITCH / 2) + col];
        olo[(size_t)row * 576 + col] = slo32[row * (SPITCH / 2) + col];
    }
}

// ---------------- 6. main contraction: bf16x3 mma.sync, 3-stage pipeline + fused gates ----------------
#define KC 32
#define APITCH 40
#define AHB (256 * APITCH * 2)             // 20480
#define BHB (128 * APITCH * 2)             // 10240
#define OFF_AL AHB
#define OFF_BH (2 * AHB)
#define OFF_BL (2 * AHB + BHB)
#define STG (2 * AHB + 2 * BHB)            // 61440
#define NSTAGE 3
#define GSMEM (NSTAGE * STG)               // 184320 (>= epilogue 135168)

__global__ __launch_bounds__(512, 1) void k_gemm_mma(const float* __restrict__ ccur,
                                                     float* __restrict__ out) {
    extern __shared__ char smb[];
    uint32_t s0 = smem_u32(smb);
    int tid = threadIdx.x, wid = tid >> 5, lane = tid & 31;
    int b = blockIdx.y;
    int hw0 = blockIdx.x * 128;

    const __nv_bfloat16* Ahi = d_Ahi + (size_t)b * 256 * CN;
    const __nv_bfloat16* Alo = d_Alo + (size_t)b * 256 * CN;
    const __nv_bfloat16* Bhi = d_Bhi + (size_t)(b * HW4 + hw0) * CN;
    const __nv_bfloat16* Blo = d_Blo + (size_t)(b * HW4 + hw0) * CN;

    auto load_stage = [&](int stage, int k0) {
        uint32_t sa = s0 + stage * STG;
        #pragma unroll
        for (int i = 0; i < 2; i++) {
            int l = tid + i * 512;
            int r = l >> 2, seg = l & 3;
            CP_ASYNC16(sa + r * 80 + seg * 16, Ahi + (size_t)r * CN + k0 + seg * 8);
        }
        #pragma unroll
        for (int i = 0; i < 2; i++) {
            int l = tid + i * 512;
            int r = l >> 2, seg = l & 3;
            CP_ASYNC16(sa + OFF_AL + r * 80 + seg * 16, Alo + (size_t)r * CN + k0 + seg * 8);
        }
        {
            int r = tid >> 2, seg = tid & 3;
            CP_ASYNC16(sa + OFF_BH + r * 80 + seg * 16, Bhi + (size_t)r * CN + k0 + seg * 8);
            CP_ASYNC16(sa + OFF_BL + r * 80 + seg * 16, Blo + (size_t)r * CN + k0 + seg * 8);
        }
    };

    float acc[4][4][4];
    #pragma unroll
    for (int i = 0; i < 4; i++)
        #pragma unroll
        for (int j = 0; j < 4; j++)
            #pragma unroll
            for (int q = 0; q < 4; q++) acc[i][j][q] = 0.f;

    load_stage(0, 0); CP_COMMIT();
    load_stage(1, KC); CP_COMMIT();

    int mwarp = (wid & 3) * 64;
    int nwarp = (wid >> 2) * 32;
    int grp = lane >> 2, tig = lane & 3;
    uint32_t aRow = (uint32_t)(mwarp + (lane & 15)) * 80 + (((uint32_t)lane >> 4) << 4);
    int lB = lane & 15;
    uint32_t bRow = (uint32_t)(nwarp + (lB & 7)) * 80 + ((((uint32_t)lB >> 3) & 1) << 4);

    for (int it = 0; it < 36; it++) {
        int cur = it % NSTAGE;
        if (it + 1 < 36) { CP_WAIT(1); } else { CP_WAIT(0); }
        __syncthreads();
        // prefetch stage it+2 (slot freed at iter it-1; end-of-prev-iter barrier makes it safe)
        if (it + 2 < 36) {
            load_stage((it + 2) % NSTAGE, (it + 2) * KC);
            CP_COMMIT();
        }
        uint32_t base = s0 + cur * STG;
        #pragma unroll
        for (int s = 0; s < 2; s++) {
            uint32_t kof = (uint32_t)s * 32;
            uint32_t bh[4][2], bl[4][2];
            #pragma unroll
            for (int nt = 0; nt < 4; nt++) {
                uint32_t ab = base + OFF_BH + bRow + nt * (8 * 80) + kof;
                LDSM_X2(bh[nt][0], bh[nt][1], ab);
                LDSM_X2(bl[nt][0], bl[nt][1], ab + BHB);
            }
            #pragma unroll
            for (int mt = 0; mt < 4; mt++) {
                uint32_t aa = base + aRow + mt * (16 * 80) + kof;
                uint32_t ah[4], al[4];
                LDSM_X4(ah[0], ah[1], ah[2], ah[3], aa);
                LDSM_X4(al[0], al[1], al[2], al[3], aa + AHB);
                #pragma unroll
                for (int nt = 0; nt < 4; nt++) {
                    mma_bf16(acc[mt][nt], ah, bh[nt]);
                    mma_bf16(acc[mt][nt], ah, bl[nt]);
                    mma_bf16(acc[mt][nt], al, bh[nt]);
                }
            }
        }
        __syncthreads();
    }

    // ---- stage C tile (with bias) into smem, then fused LSTM gates ----
    float* Cs = (float*)smb;               // [256][132]
    const float* bmp = d_bm + b * 256;
    #pragma unroll
    for (int mt = 0; mt < 4; mt++) {
        int row = mwarp + mt * 16 + grp;
        float bz0 = bmp[row], bz1 = bmp[row + 8];
        #pragma unroll
        for (int nt = 0; nt < 4; nt++) {
            int col = nwarp + nt * 8 + tig * 2;
            Cs[row * 132 + col]           = acc[mt][nt][0] + bz0;
            Cs[row * 132 + col + 1]       = acc[mt][nt][1] + bz0;
            Cs[(row + 8) * 132 + col]     = acc[mt][nt][2] + bz1;
            Cs[(row + 8) * 132 + col + 1] = acc[mt][nt][3] + bz1;
        }
    }
    __syncthreads();
    #pragma unroll
    for (int q = 0; q < 16; q++) {
        int lin = q * 512 + tid;           // < 8192
        int hid = lin >> 7, hw = lin & 127;
        float ci = Cs[hid * 132 + hw];
        float cf = Cs[(hid + 64) * 132 + hw];
        float co = Cs[(hid + 128) * 132 + hw];
        float cg = Cs[(hid + 192) * 132 + hw];
        float ig = 1.f / (1.f + expf(-ci));
        float fg = 1.f / (1.f + expf(-cf));
        float og = 1.f / (1.f + expf(-co));
        float gg = tanhf(cg);
        int g = (b * 64 + hid) * HW4 + hw0 + hw;
        float cn = fg * ccur[g] + ig * gg;
        float hn = og * tanhf(cn);
        out[g] = hn;
        out[1048576 + g] = cn;
    }
}

// ---------------- launch ----------------
extern "C" void kernel_launch(void* const* d_in, const int* in_sizes, int n_in,
                              void* d_out, int out_size) {
    const float* inp  = (const float*)d_in[0];
    const float* hcur = (const float*)d_in[1];
    const float* ccur = (const float*)d_in[2];
    const float* meta = (const float*)d_in[3];
    const float* mio  = (const float*)d_in[4];
    const float* w1w  = (const float*)d_in[5];
    const float* w1b  = (const float*)d_in[6];
    const float* w2w  = (const float*)d_in[7];
    const float* w2b  = (const float*)d_in[8];
    const float* blw  = (const float*)d_in[9];
    const float* blb  = (const float*)d_in[10];
    const float* pw   = (const float*)d_in[11];
    const float* pb   = (const float*)d_in[12];
    float* out = (float*)d_out;

    cudaFuncSetAttribute(k_hyper2, cudaFuncAttributeMaxDynamicSharedMemorySize, 2 * H2STG);
    cudaFuncSetAttribute(k_sample_t, cudaFuncAttributeMaxDynamicSharedMemorySize,
                         2 * 16 * SPITCH * 2);
    cudaFuncSetAttribute(k_gemm_mma, cudaFuncAttributeMaxDynamicSharedMemorySize, GSMEM);

    k_w1      <<<4096, 256>>>(meta, w1w, w1b);
    k_wb      <<<2432, 256>>>(w2w, meta, blw, blb);
    k_offset  <<<dim3(16, 4), 256>>>(mio, pw, pb);
    k_hyper2  <<<dim3(18, 4), 256, 2 * H2STG>>>(w2b);
    k_sample_t<<<dim3(256, 4), 256, 2 * 16 * SPITCH * 2>>>(inp, hcur);
    k_gemm_mma<<<dim3(32, 4), 512, GSMEM>>>(ccur, out);
}